// round 1
// baseline (speedup 1.0000x reference)
#include <cuda_runtime.h>
#include <cuda_fp16.h>

// Problem dims
#define TT 512
#define BB 256
#define SS 64
#define HH 128
#define NROW (TT*BB)          // 131072
#define PAD 132               // smem row pad (floats)

// ---------------- scratch (device globals; no allocation allowed) ----------------
__device__ float g_f2[(size_t)2 * NROW * HH];        // post-MLP features, both nets (134MB)
__device__ float g_gx[(size_t)2 * NROW * 4 * HH];    // gx = f2@wih.T + bih + bhh   (536MB)
__device__ float g_h [(size_t)2 * NROW * HH];        // LSTM hidden outputs          (134MB)
__device__ __half g_wpk[2 * 65536];                  // packed whh fp16 [k][j][gate]

// ---------------- helpers ----------------
__device__ __forceinline__ float sigf(float x) {
    return __fdividef(1.f, 1.f + __expf(-x));
}
__device__ __forceinline__ float tanhfast(float x) {
    return __fdividef(2.f, 1.f + __expf(-2.f * x)) - 1.f;
}

// ---------------- pack whh -> fp16 [k][j][g] ----------------
__global__ void pack_kernel(const float* __restrict__ a_whh, const float* __restrict__ c_whh) {
    int idx = blockIdx.x * blockDim.x + threadIdx.x;  // 0 .. 131071
    if (idx >= 2 * 65536) return;
    int net = idx >> 16;
    int r = idx & 65535;
    int g = r & 3;
    int j = (r >> 2) & 127;
    int k = r >> 9;
    const float* w = net ? c_whh : a_whh;
    g_wpk[idx] = __float2half(w[(g * 128 + j) * 128 + k]);
}

// ---------------- fused 2-layer MLP (relu) : state[128rows x 64] -> f2[128 x 128] ----------------
// smem: Xs[128*64] | W1s[64*PAD] (transposed) | F1s[128*PAD] | W2s[128*PAD] (transposed)
#define MLP_SMEM ((128*64 + 64*PAD + 128*PAD + 128*PAD) * 4)

__global__ void __launch_bounds__(256) mlp_kernel(
    const float* __restrict__ x,
    const float* __restrict__ w1, const float* __restrict__ b1,
    const float* __restrict__ w2, const float* __restrict__ b2, int net)
{
    extern __shared__ float sm[];
    float* Xs  = sm;                    // 128*64
    float* W1s = Xs + 128 * 64;         // 64*PAD
    float* F1s = W1s + 64 * PAD;        // 128*PAD
    float* W2s = F1s + 128 * PAD;       // 128*PAD
    int tid = threadIdx.x;
    size_t rowbase = (size_t)blockIdx.x * 128;

    // load X (coalesced float4)
    {
        const float4* xg = (const float4*)(x + rowbase * SS);
        float4* xs4 = (float4*)Xs;
        for (int i = tid; i < 128 * 16; i += 256) xs4[i] = xg[i];
    }
    // load W1 transposed: W1s[k][c] = w1[c][k]
    for (int i = tid; i < 128 * 64; i += 256) {
        int c = i >> 6, k = i & 63;
        W1s[k * PAD + c] = w1[i];
    }
    // load W2 transposed
    for (int i = tid; i < 128 * 128; i += 256) {
        int c = i >> 7, k = i & 127;
        W2s[k * PAD + c] = w2[i];
    }
    __syncthreads();

    int tc = tid & 15, tr = tid >> 4;
    int c0 = tc * 8, r0 = tr * 8;
    float acc[8][8];

    // -------- stage A: F1 = relu(X @ W1.T + b1), K = 64 --------
    #pragma unroll
    for (int i = 0; i < 8; i++)
        #pragma unroll
        for (int j = 0; j < 8; j++) acc[i][j] = 0.f;

    for (int k = 0; k < 64; k += 4) {
        float4 av[8];
        #pragma unroll
        for (int i = 0; i < 8; i++) av[i] = *(const float4*)(Xs + (r0 + i) * 64 + k);
        #pragma unroll
        for (int kk = 0; kk < 4; kk++) {
            float4 bva = *(const float4*)(W1s + (k + kk) * PAD + c0);
            float4 bvb = *(const float4*)(W1s + (k + kk) * PAD + c0 + 4);
            float bb[8] = {bva.x, bva.y, bva.z, bva.w, bvb.x, bvb.y, bvb.z, bvb.w};
            #pragma unroll
            for (int i = 0; i < 8; i++) {
                float a = ((const float*)&av[i])[kk];
                #pragma unroll
                for (int j = 0; j < 8; j++) acc[i][j] += a * bb[j];
            }
        }
    }
    {
        float bj[8];
        #pragma unroll
        for (int j = 0; j < 8; j++) bj[j] = __ldg(b1 + c0 + j);
        #pragma unroll
        for (int i = 0; i < 8; i++)
            #pragma unroll
            for (int j = 0; j < 8; j++) {
                float v = acc[i][j] + bj[j];
                F1s[(r0 + i) * PAD + c0 + j] = v > 0.f ? v : 0.f;
            }
    }
    __syncthreads();

    // -------- stage B: F2 = relu(F1 @ W2.T + b2), K = 128 --------
    #pragma unroll
    for (int i = 0; i < 8; i++)
        #pragma unroll
        for (int j = 0; j < 8; j++) acc[i][j] = 0.f;

    for (int k = 0; k < 128; k += 4) {
        float4 av[8];
        #pragma unroll
        for (int i = 0; i < 8; i++) av[i] = *(const float4*)(F1s + (r0 + i) * PAD + k);
        #pragma unroll
        for (int kk = 0; kk < 4; kk++) {
            float4 bva = *(const float4*)(W2s + (k + kk) * PAD + c0);
            float4 bvb = *(const float4*)(W2s + (k + kk) * PAD + c0 + 4);
            float bb[8] = {bva.x, bva.y, bva.z, bva.w, bvb.x, bvb.y, bvb.z, bvb.w};
            #pragma unroll
            for (int i = 0; i < 8; i++) {
                float a = ((const float*)&av[i])[kk];
                #pragma unroll
                for (int j = 0; j < 8; j++) acc[i][j] += a * bb[j];
            }
        }
    }
    {
        float* outp = g_f2 + (size_t)net * NROW * HH;
        float bj[8];
        #pragma unroll
        for (int j = 0; j < 8; j++) bj[j] = __ldg(b2 + c0 + j);
        #pragma unroll
        for (int i = 0; i < 8; i++) {
            float4 o0, o1;
            float v;
            v = acc[i][0] + bj[0]; o0.x = v > 0.f ? v : 0.f;
            v = acc[i][1] + bj[1]; o0.y = v > 0.f ? v : 0.f;
            v = acc[i][2] + bj[2]; o0.z = v > 0.f ? v : 0.f;
            v = acc[i][3] + bj[3]; o0.w = v > 0.f ? v : 0.f;
            v = acc[i][4] + bj[4]; o1.x = v > 0.f ? v : 0.f;
            v = acc[i][5] + bj[5]; o1.y = v > 0.f ? v : 0.f;
            v = acc[i][6] + bj[6]; o1.z = v > 0.f ? v : 0.f;
            v = acc[i][7] + bj[7]; o1.w = v > 0.f ? v : 0.f;
            size_t base = (rowbase + r0 + i) * (size_t)HH + c0;
            *(float4*)(outp + base)     = o0;
            *(float4*)(outp + base + 4) = o1;
        }
    }
}

// ---------------- gx GEMM: gx = f2 @ wih.T + (bih+bhh) ----------------
// grid (1024 row-tiles, 4 col-chunks of 128)
#define GX_SMEM ((128*PAD + 128*PAD) * 4)

__global__ void __launch_bounds__(256) gx_kernel(
    const float* __restrict__ wih,
    const float* __restrict__ bih, const float* __restrict__ bhh, int net)
{
    extern __shared__ float sm[];
    float* As = sm;                 // 128*PAD (f2 tile)
    float* Bs = As + 128 * PAD;     // 128*PAD (wih chunk transposed)
    int tid = threadIdx.x;
    size_t rowbase = (size_t)blockIdx.x * 128;
    int chunk = blockIdx.y;         // 0..3

    const float* f2 = g_f2 + (size_t)net * NROW * HH;
    // load A tile
    for (int i = tid; i < 128 * 32; i += 256) {
        int r = i >> 5, k4 = i & 31;
        *(float4*)(As + r * PAD + k4 * 4) =
            *(const float4*)(f2 + (rowbase + r) * (size_t)HH + k4 * 4);
    }
    // load B transposed: Bs[k][c] = wih[chunk*128 + c][k]
    for (int i = tid; i < 128 * 128; i += 256) {
        int c = i >> 7, k = i & 127;
        Bs[k * PAD + c] = wih[(size_t)(chunk * 128 + c) * 128 + k];
    }
    __syncthreads();

    int tc = tid & 15, tr = tid >> 4;
    int c0 = tc * 8, r0 = tr * 8;
    float acc[8][8];
    #pragma unroll
    for (int i = 0; i < 8; i++)
        #pragma unroll
        for (int j = 0; j < 8; j++) acc[i][j] = 0.f;

    for (int k = 0; k < 128; k += 4) {
        float4 av[8];
        #pragma unroll
        for (int i = 0; i < 8; i++) av[i] = *(const float4*)(As + (r0 + i) * PAD + k);
        #pragma unroll
        for (int kk = 0; kk < 4; kk++) {
            float4 bva = *(const float4*)(Bs + (k + kk) * PAD + c0);
            float4 bvb = *(const float4*)(Bs + (k + kk) * PAD + c0 + 4);
            float bb[8] = {bva.x, bva.y, bva.z, bva.w, bvb.x, bvb.y, bvb.z, bvb.w};
            #pragma unroll
            for (int i = 0; i < 8; i++) {
                float a = ((const float*)&av[i])[kk];
                #pragma unroll
                for (int j = 0; j < 8; j++) acc[i][j] += a * bb[j];
            }
        }
    }
    {
        float* outp = g_gx + (size_t)net * NROW * 4 * HH;
        int gc = chunk * 128 + c0;
        float bj[8];
        #pragma unroll
        for (int j = 0; j < 8; j++) bj[j] = __ldg(bih + gc + j) + __ldg(bhh + gc + j);
        #pragma unroll
        for (int i = 0; i < 8; i++) {
            float4 o0, o1;
            o0.x = acc[i][0] + bj[0]; o0.y = acc[i][1] + bj[1];
            o0.z = acc[i][2] + bj[2]; o0.w = acc[i][3] + bj[3];
            o1.x = acc[i][4] + bj[4]; o1.y = acc[i][5] + bj[5];
            o1.z = acc[i][6] + bj[6]; o1.w = acc[i][7] + bj[7];
            size_t base = (rowbase + r0 + i) * (size_t)512 + gc;
            *(float4*)(outp + base)     = o0;
            *(float4*)(outp + base + 4) = o1;
        }
    }
}

// ---------------- LSTM: persistent CTAs, batch-partitioned, whh fp16 in smem ----------------
// grid 128 CTAs: cta 0..63 actor (4 batch rows each), 64..127 critic
#define LSTM_SMEM (65536*2 + 2*4*128*4)   // wpk fp16 + double-buffered h

__global__ void __launch_bounds__(256) lstm_kernel(const int* __restrict__ dones) {
    extern __shared__ char smraw[];
    __half* wpk = (__half*)smraw;                 // 65536 halves, layout [k][j][gate]
    float* hbuf = (float*)(smraw + 65536 * 2);    // [2][4][128]
    int tid = threadIdx.x;
    int cta = blockIdx.x;
    int net = cta >> 6;
    int rb  = (cta & 63) << 2;

    // stage weights into smem
    {
        const int4* src = (const int4*)(g_wpk + (size_t)net * 65536);
        int4* dst = (int4*)wpk;
        for (int i = tid; i < 8192; i += 256) dst[i] = src[i];
    }
    for (int i = tid; i < 1024; i += 256) hbuf[i] = 0.f;
    __syncthreads();

    int j = tid & 127, rp = tid >> 7;
    int r0 = rb + rp * 2;                         // this thread: rows r0, r0+1; hidden col j
    float cc0 = 0.f, cc1 = 0.f;
    const float* gxp = g_gx + (size_t)net * NROW * 512;
    float* hout = g_h + (size_t)net * NROW * HH;
    const __half* wp = wpk + j * 4;
    int buf = 0;

    for (int t = 0; t < TT; ++t) {
        int row0 = t * BB + r0;
        size_t gb = (size_t)row0 * 512 + j;
        // prefetch gx + dones (consumed only in epilogue -> latency hidden)
        float gx00 = gxp[gb],        gx01 = gxp[gb + 128];
        float gx02 = gxp[gb + 256],  gx03 = gxp[gb + 384];
        float gx10 = gxp[gb + 512],  gx11 = gxp[gb + 640];
        float gx12 = gxp[gb + 768],  gx13 = gxp[gb + 896];
        int d0 = dones[row0], d1 = dones[row0 + 1];

        float a00 = 0.f, a01 = 0.f, a02 = 0.f, a03 = 0.f;
        float a10 = 0.f, a11 = 0.f, a12 = 0.f, a13 = 0.f;
        const float* hp0 = hbuf + buf * 512 + (rp * 2) * 128;
        const float* hp1 = hp0 + 128;

        #pragma unroll 2
        for (int k = 0; k < 128; k += 4) {
            float4 h0v = *(const float4*)(hp0 + k);
            float4 h1v = *(const float4*)(hp1 + k);
            #pragma unroll
            for (int kk = 0; kk < 4; kk++) {
                uint2 wraw = *(const uint2*)(wp + (k + kk) * 512);
                float2 w01 = __half22float2(*(const __half2*)&wraw.x);
                float2 w23 = __half22float2(*(const __half2*)&wraw.y);
                float h0 = ((const float*)&h0v)[kk];
                float h1 = ((const float*)&h1v)[kk];
                a00 += h0 * w01.x; a01 += h0 * w01.y; a02 += h0 * w23.x; a03 += h0 * w23.y;
                a10 += h1 * w01.x; a11 += h1 * w01.y; a12 += h1 * w23.x; a13 += h1 * w23.y;
            }
        }

        float* hn = hbuf + (buf ^ 1) * 512 + (rp * 2) * 128;
        // row 0
        {
            float ig = sigf(a00 + gx00);
            float fg = sigf(a01 + gx01);
            float gg = tanhfast(a02 + gx02);
            float og = sigf(a03 + gx03);
            float c2 = fg * cc0 + ig * gg;
            float h2 = og * tanhfast(c2);
            hout[(size_t)row0 * HH + j] = h2;
            float m = 1.f - (float)d0;
            cc0 = c2 * m;
            hn[j] = h2 * m;
        }
        // row 1
        {
            float ig = sigf(a10 + gx10);
            float fg = sigf(a11 + gx11);
            float gg = tanhfast(a12 + gx12);
            float og = sigf(a13 + gx13);
            float c2 = fg * cc1 + ig * gg;
            float h2 = og * tanhfast(c2);
            hout[(size_t)(row0 + 1) * HH + j] = h2;
            float m = 1.f - (float)d1;
            cc1 = c2 * m;
            hn[128 + j] = h2 * m;
        }
        __syncthreads();
        buf ^= 1;
    }
}

// ---------------- heads: warp per row, shfl reductions ----------------
__global__ void __launch_bounds__(256) heads_kernel(
    const float* __restrict__ mw, const float* __restrict__ mb,
    const float* __restrict__ lw, const float* __restrict__ lb,
    const float* __restrict__ vw, const float* __restrict__ vb,
    float* __restrict__ out)
{
    __shared__ float ws[17][128];
    __shared__ float bs[17];
    int tid = threadIdx.x;
    for (int i = tid; i < 8 * 128; i += 256) {
        ws[i >> 7][i & 127]       = mw[i];
        ws[8 + (i >> 7)][i & 127] = lw[i];
    }
    for (int i = tid; i < 128; i += 256) ws[16][i] = vw[i];
    if (tid < 8) { bs[tid] = mb[tid]; bs[8 + tid] = lb[tid]; }
    if (tid == 16) bs[16] = vb[0];
    __syncthreads();

    int warp = tid >> 5, lane = tid & 31;
    int row = blockIdx.x * 8 + warp;

    const float* ha = g_h + (size_t)row * HH;
    const float* hc = g_h + (size_t)NROW * HH + (size_t)row * HH;
    float4 av = *(const float4*)(ha + lane * 4);
    float4 cv = *(const float4*)(hc + lane * 4);

    float p[17];
    #pragma unroll
    for (int o = 0; o < 16; o++) {
        float4 wv = *(const float4*)(&ws[o][lane * 4]);
        p[o] = av.x * wv.x + av.y * wv.y + av.z * wv.z + av.w * wv.w;
    }
    {
        float4 wv = *(const float4*)(&ws[16][lane * 4]);
        p[16] = cv.x * wv.x + cv.y * wv.y + cv.z * wv.z + cv.w * wv.w;
    }
    #pragma unroll
    for (int o = 0; o < 17; o++) {
        p[o] += __shfl_xor_sync(0xffffffff, p[o], 16);
        p[o] += __shfl_xor_sync(0xffffffff, p[o], 8);
        p[o] += __shfl_xor_sync(0xffffffff, p[o], 4);
        p[o] += __shfl_xor_sync(0xffffffff, p[o], 2);
        p[o] += __shfl_xor_sync(0xffffffff, p[o], 1);
    }
    if (lane < 8) {
        out[(size_t)row * 8 + lane] = p[lane] + bs[lane];
    } else if (lane < 16) {
        out[(size_t)NROW * 8 + (size_t)row * 8 + (lane - 8)] = __expf(p[lane] + bs[lane]);
    } else if (lane == 16) {
        out[(size_t)NROW * 16 + row] = p[16] + bs[16];
    }
}

// ---------------- launch ----------------
extern "C" void kernel_launch(void* const* d_in, const int* in_sizes, int n_in,
                              void* d_out, int out_size)
{
    const float* state  = (const float*)d_in[0];
    const int*   dones  = (const int*)d_in[1];
    const float* a_w1   = (const float*)d_in[2];
    const float* a_b1   = (const float*)d_in[3];
    const float* a_w2   = (const float*)d_in[4];
    const float* a_b2   = (const float*)d_in[5];
    const float* c_w1   = (const float*)d_in[6];
    const float* c_b1   = (const float*)d_in[7];
    const float* c_w2   = (const float*)d_in[8];
    const float* c_b2   = (const float*)d_in[9];
    const float* a_wih  = (const float*)d_in[10];
    const float* a_whh  = (const float*)d_in[11];
    const float* a_bih  = (const float*)d_in[12];
    const float* a_bhh  = (const float*)d_in[13];
    const float* c_wih  = (const float*)d_in[14];
    const float* c_whh  = (const float*)d_in[15];
    const float* c_bih  = (const float*)d_in[16];
    const float* c_bhh  = (const float*)d_in[17];
    const float* mean_w = (const float*)d_in[18];
    const float* mean_b = (const float*)d_in[19];
    const float* lstd_w = (const float*)d_in[20];
    const float* lstd_b = (const float*)d_in[21];
    const float* val_w  = (const float*)d_in[22];
    const float* val_b  = (const float*)d_in[23];

    cudaFuncSetAttribute(mlp_kernel,  cudaFuncAttributeMaxDynamicSharedMemorySize, MLP_SMEM);
    cudaFuncSetAttribute(gx_kernel,   cudaFuncAttributeMaxDynamicSharedMemorySize, GX_SMEM);
    cudaFuncSetAttribute(lstm_kernel, cudaFuncAttributeMaxDynamicSharedMemorySize, LSTM_SMEM);

    pack_kernel<<<512, 256>>>(a_whh, c_whh);

    mlp_kernel<<<1024, 256, MLP_SMEM>>>(state, a_w1, a_b1, a_w2, a_b2, 0);
    mlp_kernel<<<1024, 256, MLP_SMEM>>>(state, c_w1, c_b1, c_w2, c_b2, 1);

    dim3 gxg(1024, 4);
    gx_kernel<<<gxg, 256, GX_SMEM>>>(a_wih, a_bih, a_bhh, 0);
    gx_kernel<<<gxg, 256, GX_SMEM>>>(c_wih, c_bih, c_bhh, 1);

    lstm_kernel<<<128, 256, LSTM_SMEM>>>(dones);

    heads_kernel<<<NROW / 8, 256>>>(mean_w, mean_b, lstd_w, lstd_b,
                                    val_w, val_b, (float*)d_out);
}

// round 2
// speedup vs baseline: 1.5858x; 1.5858x over previous
#include <cuda_runtime.h>
#include <cuda_fp16.h>

// Problem dims
#define TT 512
#define BB 256
#define SS 64
#define HH 128
#define NROW (TT*BB)          // 131072

// ---------------- scratch (device globals; no allocation allowed) ----------------
__device__ __half g_f2h[(size_t)2 * NROW * HH];      // post-MLP features fp16 (67MB)
__device__ __half g_gxh[(size_t)2 * NROW * 512];     // gx fp16 (268MB)
__device__ __half g_hh [(size_t)2 * NROW * HH];      // LSTM hidden outputs fp16 (67MB)
__device__ __half g_wpk[2 * 65536];                  // packed whh fp16 [k][j][gate]

// ---------------- helpers ----------------
__device__ __forceinline__ float sigf(float x) {
    return __fdividef(1.f, 1.f + __expf(-x));
}
__device__ __forceinline__ float tanhfast(float x) {
    return __fdividef(2.f, 1.f + __expf(-2.f * x)) - 1.f;
}
__device__ __forceinline__ void mma16816(float* c, const unsigned* a, const unsigned* b) {
    asm volatile(
        "mma.sync.aligned.m16n8k16.row.col.f32.f16.f16.f32 "
        "{%0,%1,%2,%3}, {%4,%5,%6,%7}, {%8,%9}, {%0,%1,%2,%3};\n"
        : "+f"(c[0]), "+f"(c[1]), "+f"(c[2]), "+f"(c[3])
        : "r"(a[0]), "r"(a[1]), "r"(a[2]), "r"(a[3]), "r"(b[0]), "r"(b[1]));
}
__device__ __forceinline__ void ldsm4(unsigned* d, const __half* p) {
    unsigned addr = (unsigned)__cvta_generic_to_shared(p);
    asm volatile("ldmatrix.sync.aligned.m8n8.x4.shared.b16 {%0,%1,%2,%3}, [%4];\n"
                 : "=r"(d[0]), "=r"(d[1]), "=r"(d[2]), "=r"(d[3]) : "r"(addr));
}

// ---------------- pack whh -> fp16 [k][j][gate] for the LSTM ----------------
__global__ void pack_kernel(const float* __restrict__ a_whh, const float* __restrict__ c_whh) {
    int idx = blockIdx.x * blockDim.x + threadIdx.x;
    if (idx >= 2 * 65536) return;
    int net = idx >> 16;
    int r = idx & 65535;
    int g = r & 3;
    int j = (r >> 2) & 127;
    int k = r >> 9;
    const float* w = net ? c_whh : a_whh;
    g_wpk[idx] = __float2half(w[(g * 128 + j) * 128 + k]);
}

// =====================================================================
// Tensor-core fused MLP: f2 = relu(relu(X@W1.T+b1)@W2.T+b2)  (fp16 HMMA)
// Block: 256 thr (8 warps as 4m x 2n), row tile 128.
// smem halves: Xs[128][72] | W1s[128][72] | W2s[128][136] | C1s[128][136]
// =====================================================================
#define XS_STR 72
#define MH_STR 136
#define MLP_SMEM (2048 + (128*XS_STR + 128*XS_STR + 128*MH_STR + 128*MH_STR) * 2)

__global__ void __launch_bounds__(256) mlp16_kernel(
    const float* __restrict__ x,
    const float* __restrict__ w1, const float* __restrict__ b1,
    const float* __restrict__ w2, const float* __restrict__ b2, int net)
{
    extern __shared__ __align__(16) char smraw[];
    float* bs1 = (float*)smraw;            // 128
    float* bs2 = bs1 + 128;                // 128
    __half* Xs  = (__half*)(smraw + 2048);
    __half* W1s = Xs  + 128 * XS_STR;
    __half* W2s = W1s + 128 * XS_STR;
    __half* C1s = W2s + 128 * MH_STR;

    int tid = threadIdx.x;
    size_t rowbase = (size_t)blockIdx.x * 128;

    // ---- loads: convert fp32 -> fp16 smem ----
    {   // X [128][64]
        const float4* xg = (const float4*)(x + rowbase * SS);
        for (int i = tid; i < 128 * 16; i += 256) {
            int r = i >> 4, c4 = i & 15;
            float4 v = xg[(size_t)r * 16 + c4];
            *(__half2*)&Xs[r * XS_STR + c4 * 4]     = __floats2half2_rn(v.x, v.y);
            *(__half2*)&Xs[r * XS_STR + c4 * 4 + 2] = __floats2half2_rn(v.z, v.w);
        }
    }
    {   // W1 [128][64]
        const float4* wg = (const float4*)w1;
        for (int i = tid; i < 128 * 16; i += 256) {
            int r = i >> 4, c4 = i & 15;
            float4 v = wg[(size_t)r * 16 + c4];
            *(__half2*)&W1s[r * XS_STR + c4 * 4]     = __floats2half2_rn(v.x, v.y);
            *(__half2*)&W1s[r * XS_STR + c4 * 4 + 2] = __floats2half2_rn(v.z, v.w);
        }
    }
    {   // W2 [128][128]
        const float4* wg = (const float4*)w2;
        for (int i = tid; i < 128 * 32; i += 256) {
            int r = i >> 5, c4 = i & 31;
            float4 v = wg[(size_t)r * 32 + c4];
            *(__half2*)&W2s[r * MH_STR + c4 * 4]     = __floats2half2_rn(v.x, v.y);
            *(__half2*)&W2s[r * MH_STR + c4 * 4 + 2] = __floats2half2_rn(v.z, v.w);
        }
    }
    if (tid < 128) { bs1[tid] = __ldg(b1 + tid); bs2[tid] = __ldg(b2 + tid); }
    __syncthreads();

    int wid = tid >> 5, lane = tid & 31;
    int warp_m = wid & 3, warp_n = wid >> 2;     // 32 rows x 64 cols per warp
    int m_base = warp_m * 32, n_base = warp_n * 64;

    float acc[2][8][4];

    // -------- stage A: C1 = relu(X @ W1.T + b1), K=64 --------
    #pragma unroll
    for (int mt = 0; mt < 2; mt++)
        #pragma unroll
        for (int nt = 0; nt < 8; nt++)
            #pragma unroll
            for (int q = 0; q < 4; q++) acc[mt][nt][q] = 0.f;

    #pragma unroll
    for (int kt = 0; kt < 4; kt++) {
        int k0 = kt * 16;
        unsigned a[2][4], b[8][2];
        #pragma unroll
        for (int mt = 0; mt < 2; mt++) {
            int r = m_base + mt * 16 + (lane & 15);
            int c = k0 + ((lane >> 4) << 3);
            ldsm4(a[mt], Xs + r * XS_STR + c);
        }
        #pragma unroll
        for (int np = 0; np < 4; np++) {
            int n0 = n_base + np * 16;
            int rr = n0 + ((lane >> 4) << 3) + (lane & 7);
            int cc = k0 + (((lane >> 3) & 1) << 3);
            unsigned t4[4];
            ldsm4(t4, W1s + rr * XS_STR + cc);
            b[np * 2][0] = t4[0]; b[np * 2][1] = t4[1];
            b[np * 2 + 1][0] = t4[2]; b[np * 2 + 1][1] = t4[3];
        }
        #pragma unroll
        for (int mt = 0; mt < 2; mt++)
            #pragma unroll
            for (int nt = 0; nt < 8; nt++)
                mma16816(acc[mt][nt], a[mt], b[nt]);
    }
    // epilogue A -> C1s (fp16, relu+bias)
    #pragma unroll
    for (int mt = 0; mt < 2; mt++) {
        #pragma unroll
        for (int nt = 0; nt < 8; nt++) {
            int r = m_base + mt * 16 + (lane >> 2);
            int c = n_base + nt * 8 + 2 * (lane & 3);
            float v0 = fmaxf(acc[mt][nt][0] + bs1[c], 0.f);
            float v1 = fmaxf(acc[mt][nt][1] + bs1[c + 1], 0.f);
            float v2 = fmaxf(acc[mt][nt][2] + bs1[c], 0.f);
            float v3 = fmaxf(acc[mt][nt][3] + bs1[c + 1], 0.f);
            *(__half2*)&C1s[r * MH_STR + c]       = __floats2half2_rn(v0, v1);
            *(__half2*)&C1s[(r + 8) * MH_STR + c] = __floats2half2_rn(v2, v3);
        }
    }
    __syncthreads();

    // -------- stage B: F2 = relu(C1 @ W2.T + b2), K=128 --------
    #pragma unroll
    for (int mt = 0; mt < 2; mt++)
        #pragma unroll
        for (int nt = 0; nt < 8; nt++)
            #pragma unroll
            for (int q = 0; q < 4; q++) acc[mt][nt][q] = 0.f;

    #pragma unroll
    for (int kt = 0; kt < 8; kt++) {
        int k0 = kt * 16;
        unsigned a[2][4], b[8][2];
        #pragma unroll
        for (int mt = 0; mt < 2; mt++) {
            int r = m_base + mt * 16 + (lane & 15);
            int c = k0 + ((lane >> 4) << 3);
            ldsm4(a[mt], C1s + r * MH_STR + c);
        }
        #pragma unroll
        for (int np = 0; np < 4; np++) {
            int n0 = n_base + np * 16;
            int rr = n0 + ((lane >> 4) << 3) + (lane & 7);
            int cc = k0 + (((lane >> 3) & 1) << 3);
            unsigned t4[4];
            ldsm4(t4, W2s + rr * MH_STR + cc);
            b[np * 2][0] = t4[0]; b[np * 2][1] = t4[1];
            b[np * 2 + 1][0] = t4[2]; b[np * 2 + 1][1] = t4[3];
        }
        #pragma unroll
        for (int mt = 0; mt < 2; mt++)
            #pragma unroll
            for (int nt = 0; nt < 8; nt++)
                mma16816(acc[mt][nt], a[mt], b[nt]);
    }
    // epilogue B -> g_f2h
    {
        __half* outp = g_f2h + (size_t)net * NROW * HH;
        #pragma unroll
        for (int mt = 0; mt < 2; mt++) {
            #pragma unroll
            for (int nt = 0; nt < 8; nt++) {
                int r = m_base + mt * 16 + (lane >> 2);
                int c = n_base + nt * 8 + 2 * (lane & 3);
                float v0 = fmaxf(acc[mt][nt][0] + bs2[c], 0.f);
                float v1 = fmaxf(acc[mt][nt][1] + bs2[c + 1], 0.f);
                float v2 = fmaxf(acc[mt][nt][2] + bs2[c], 0.f);
                float v3 = fmaxf(acc[mt][nt][3] + bs2[c + 1], 0.f);
                *(__half2*)(outp + (rowbase + r) * (size_t)HH + c) = __floats2half2_rn(v0, v1);
                *(__half2*)(outp + (rowbase + r + 8) * (size_t)HH + c) = __floats2half2_rn(v2, v3);
            }
        }
    }
}

// =====================================================================
// Tensor-core gx GEMM: gx = f2 @ wih.T + (bih+bhh)  (fp16 HMMA)
// grid (1024 row-tiles, 4 col-chunks of 128)
// =====================================================================
#define GX_SMEM (512 + (128*MH_STR + 128*MH_STR) * 2 + 16)

__global__ void __launch_bounds__(256) gx16_kernel(
    const float* __restrict__ wih,
    const float* __restrict__ bih, const float* __restrict__ bhh, int net)
{
    extern __shared__ __align__(16) char smraw[];
    float* bsum = (float*)smraw;           // 128
    __half* As = (__half*)(smraw + 512 + 16);
    __half* Ws = As + 128 * MH_STR;

    int tid = threadIdx.x;
    size_t rowbase = (size_t)blockIdx.x * 128;
    int chunk = blockIdx.y;                // 0..3

    {   // A tile: f2h [128][128] fp16 gmem -> smem
        const uint4* ag = (const uint4*)(g_f2h + (size_t)net * NROW * HH + rowbase * HH);
        for (int i = tid; i < 128 * 16; i += 256) {
            int r = i >> 4, c = i & 15;
            *(uint4*)&As[r * MH_STR + c * 8] = ag[(size_t)r * 16 + c];
        }
    }
    {   // W chunk [128][128] fp32 -> fp16 smem
        const float4* wg = (const float4*)(wih + (size_t)chunk * 128 * 128);
        for (int i = tid; i < 128 * 32; i += 256) {
            int r = i >> 5, c4 = i & 31;
            float4 v = wg[(size_t)r * 32 + c4];
            *(__half2*)&Ws[r * MH_STR + c4 * 4]     = __floats2half2_rn(v.x, v.y);
            *(__half2*)&Ws[r * MH_STR + c4 * 4 + 2] = __floats2half2_rn(v.z, v.w);
        }
    }
    if (tid < 128) bsum[tid] = __ldg(bih + chunk * 128 + tid) + __ldg(bhh + chunk * 128 + tid);
    __syncthreads();

    int wid = tid >> 5, lane = tid & 31;
    int warp_m = wid & 3, warp_n = wid >> 2;
    int m_base = warp_m * 32, n_base = warp_n * 64;

    float acc[2][8][4];
    #pragma unroll
    for (int mt = 0; mt < 2; mt++)
        #pragma unroll
        for (int nt = 0; nt < 8; nt++)
            #pragma unroll
            for (int q = 0; q < 4; q++) acc[mt][nt][q] = 0.f;

    #pragma unroll
    for (int kt = 0; kt < 8; kt++) {
        int k0 = kt * 16;
        unsigned a[2][4], b[8][2];
        #pragma unroll
        for (int mt = 0; mt < 2; mt++) {
            int r = m_base + mt * 16 + (lane & 15);
            int c = k0 + ((lane >> 4) << 3);
            ldsm4(a[mt], As + r * MH_STR + c);
        }
        #pragma unroll
        for (int np = 0; np < 4; np++) {
            int n0 = n_base + np * 16;
            int rr = n0 + ((lane >> 4) << 3) + (lane & 7);
            int cc = k0 + (((lane >> 3) & 1) << 3);
            unsigned t4[4];
            ldsm4(t4, Ws + rr * MH_STR + cc);
            b[np * 2][0] = t4[0]; b[np * 2][1] = t4[1];
            b[np * 2 + 1][0] = t4[2]; b[np * 2 + 1][1] = t4[3];
        }
        #pragma unroll
        for (int mt = 0; mt < 2; mt++)
            #pragma unroll
            for (int nt = 0; nt < 8; nt++)
                mma16816(acc[mt][nt], a[mt], b[nt]);
    }
    {
        __half* outp = g_gxh + (size_t)net * NROW * 512;
        #pragma unroll
        for (int mt = 0; mt < 2; mt++) {
            #pragma unroll
            for (int nt = 0; nt < 8; nt++) {
                int r = m_base + mt * 16 + (lane >> 2);
                int c = n_base + nt * 8 + 2 * (lane & 3);
                int gc = chunk * 128 + c;
                float v0 = acc[mt][nt][0] + bsum[c];
                float v1 = acc[mt][nt][1] + bsum[c + 1];
                float v2 = acc[mt][nt][2] + bsum[c];
                float v3 = acc[mt][nt][3] + bsum[c + 1];
                *(__half2*)(outp + (rowbase + r) * (size_t)512 + gc) = __floats2half2_rn(v0, v1);
                *(__half2*)(outp + (rowbase + r + 8) * (size_t)512 + gc) = __floats2half2_rn(v2, v3);
            }
        }
    }
}

// ---------------- LSTM: persistent CTAs, batch-partitioned, whh fp16 in smem ----------------
#define LSTM_SMEM (65536*2 + 2*4*128*4)

__global__ void __launch_bounds__(256) lstm_kernel(const int* __restrict__ dones) {
    extern __shared__ char smraw[];
    __half* wpk = (__half*)smraw;                 // 65536 halves, [k][j][gate]
    float* hbuf = (float*)(smraw + 65536 * 2);    // [2][4][128]
    int tid = threadIdx.x;
    int cta = blockIdx.x;
    int net = cta >> 6;
    int rb  = (cta & 63) << 2;

    {
        const int4* src = (const int4*)(g_wpk + (size_t)net * 65536);
        int4* dst = (int4*)wpk;
        for (int i = tid; i < 8192; i += 256) dst[i] = src[i];
    }
    for (int i = tid; i < 1024; i += 256) hbuf[i] = 0.f;
    __syncthreads();

    int j = tid & 127, rp = tid >> 7;
    int r0 = rb + rp * 2;
    float cc0 = 0.f, cc1 = 0.f;
    const __half* gxp = g_gxh + (size_t)net * NROW * 512;
    __half* hout = g_hh + (size_t)net * NROW * HH;
    const __half* wp = wpk + j * 4;
    int buf = 0;

    for (int t = 0; t < TT; ++t) {
        int row0 = t * BB + r0;
        size_t gb = (size_t)row0 * 512 + j;
        float gx00 = __half2float(gxp[gb]);       float gx01 = __half2float(gxp[gb + 128]);
        float gx02 = __half2float(gxp[gb + 256]); float gx03 = __half2float(gxp[gb + 384]);
        float gx10 = __half2float(gxp[gb + 512]); float gx11 = __half2float(gxp[gb + 640]);
        float gx12 = __half2float(gxp[gb + 768]); float gx13 = __half2float(gxp[gb + 896]);
        int d0 = dones[row0], d1 = dones[row0 + 1];

        float a00 = 0.f, a01 = 0.f, a02 = 0.f, a03 = 0.f;
        float a10 = 0.f, a11 = 0.f, a12 = 0.f, a13 = 0.f;
        const float* hp0 = hbuf + buf * 512 + (rp * 2) * 128;
        const float* hp1 = hp0 + 128;

        #pragma unroll 2
        for (int k = 0; k < 128; k += 4) {
            float4 h0v = *(const float4*)(hp0 + k);
            float4 h1v = *(const float4*)(hp1 + k);
            #pragma unroll
            for (int kk = 0; kk < 4; kk++) {
                uint2 wraw = *(const uint2*)(wp + (k + kk) * 512);
                float2 w01 = __half22float2(*(const __half2*)&wraw.x);
                float2 w23 = __half22float2(*(const __half2*)&wraw.y);
                float h0 = ((const float*)&h0v)[kk];
                float h1 = ((const float*)&h1v)[kk];
                a00 += h0 * w01.x; a01 += h0 * w01.y; a02 += h0 * w23.x; a03 += h0 * w23.y;
                a10 += h1 * w01.x; a11 += h1 * w01.y; a12 += h1 * w23.x; a13 += h1 * w23.y;
            }
        }

        float* hn = hbuf + (buf ^ 1) * 512 + (rp * 2) * 128;
        {
            float ig = sigf(a00 + gx00);
            float fg = sigf(a01 + gx01);
            float gg = tanhfast(a02 + gx02);
            float og = sigf(a03 + gx03);
            float c2 = fg * cc0 + ig * gg;
            float h2 = og * tanhfast(c2);
            hout[(size_t)row0 * HH + j] = __float2half(h2);
            float m = 1.f - (float)d0;
            cc0 = c2 * m;
            hn[j] = h2 * m;
        }
        {
            float ig = sigf(a10 + gx10);
            float fg = sigf(a11 + gx11);
            float gg = tanhfast(a12 + gx12);
            float og = sigf(a13 + gx13);
            float c2 = fg * cc1 + ig * gg;
            float h2 = og * tanhfast(c2);
            hout[(size_t)(row0 + 1) * HH + j] = __float2half(h2);
            float m = 1.f - (float)d1;
            cc1 = c2 * m;
            hn[128 + j] = h2 * m;
        }
        __syncthreads();
        buf ^= 1;
    }
}

// ---------------- heads: warp per row, shfl reductions (fp16 h) ----------------
__global__ void __launch_bounds__(256) heads_kernel(
    const float* __restrict__ mw, const float* __restrict__ mb,
    const float* __restrict__ lw, const float* __restrict__ lb,
    const float* __restrict__ vw, const float* __restrict__ vb,
    float* __restrict__ out)
{
    __shared__ float ws[17][128];
    __shared__ float bs[17];
    int tid = threadIdx.x;
    for (int i = tid; i < 8 * 128; i += 256) {
        ws[i >> 7][i & 127]       = mw[i];
        ws[8 + (i >> 7)][i & 127] = lw[i];
    }
    for (int i = tid; i < 128; i += 256) ws[16][i] = vw[i];
    if (tid < 8) { bs[tid] = mb[tid]; bs[8 + tid] = lb[tid]; }
    if (tid == 16) bs[16] = vb[0];
    __syncthreads();

    int warp = tid >> 5, lane = tid & 31;
    int row = blockIdx.x * 8 + warp;

    const __half2* ha = (const __half2*)(g_hh + (size_t)row * HH) + lane * 2;
    const __half2* hc = (const __half2*)(g_hh + (size_t)NROW * HH + (size_t)row * HH) + lane * 2;
    float2 a0 = __half22float2(ha[0]);
    float2 a1 = __half22float2(ha[1]);
    float2 c0 = __half22float2(hc[0]);
    float2 c1 = __half22float2(hc[1]);

    float p[17];
    #pragma unroll
    for (int o = 0; o < 16; o++) {
        float4 wv = *(const float4*)(&ws[o][lane * 4]);
        p[o] = a0.x * wv.x + a0.y * wv.y + a1.x * wv.z + a1.y * wv.w;
    }
    {
        float4 wv = *(const float4*)(&ws[16][lane * 4]);
        p[16] = c0.x * wv.x + c0.y * wv.y + c1.x * wv.z + c1.y * wv.w;
    }
    #pragma unroll
    for (int o = 0; o < 17; o++) {
        p[o] += __shfl_xor_sync(0xffffffff, p[o], 16);
        p[o] += __shfl_xor_sync(0xffffffff, p[o], 8);
        p[o] += __shfl_xor_sync(0xffffffff, p[o], 4);
        p[o] += __shfl_xor_sync(0xffffffff, p[o], 2);
        p[o] += __shfl_xor_sync(0xffffffff, p[o], 1);
    }
    if (lane < 8) {
        out[(size_t)row * 8 + lane] = p[lane] + bs[lane];
    } else if (lane < 16) {
        out[(size_t)NROW * 8 + (size_t)row * 8 + (lane - 8)] = __expf(p[lane] + bs[lane]);
    } else if (lane == 16) {
        out[(size_t)NROW * 16 + row] = p[16] + bs[16];
    }
}

// ---------------- launch ----------------
extern "C" void kernel_launch(void* const* d_in, const int* in_sizes, int n_in,
                              void* d_out, int out_size)
{
    const float* state  = (const float*)d_in[0];
    const int*   dones  = (const int*)d_in[1];
    const float* a_w1   = (const float*)d_in[2];
    const float* a_b1   = (const float*)d_in[3];
    const float* a_w2   = (const float*)d_in[4];
    const float* a_b2   = (const float*)d_in[5];
    const float* c_w1   = (const float*)d_in[6];
    const float* c_b1   = (const float*)d_in[7];
    const float* c_w2   = (const float*)d_in[8];
    const float* c_b2   = (const float*)d_in[9];
    const float* a_wih  = (const float*)d_in[10];
    const float* a_whh  = (const float*)d_in[11];
    const float* a_bih  = (const float*)d_in[12];
    const float* a_bhh  = (const float*)d_in[13];
    const float* c_wih  = (const float*)d_in[14];
    const float* c_whh  = (const float*)d_in[15];
    const float* c_bih  = (const float*)d_in[16];
    const float* c_bhh  = (const float*)d_in[17];
    const float* mean_w = (const float*)d_in[18];
    const float* mean_b = (const float*)d_in[19];
    const float* lstd_w = (const float*)d_in[20];
    const float* lstd_b = (const float*)d_in[21];
    const float* val_w  = (const float*)d_in[22];
    const float* val_b  = (const float*)d_in[23];

    cudaFuncSetAttribute(mlp16_kernel, cudaFuncAttributeMaxDynamicSharedMemorySize, MLP_SMEM);
    cudaFuncSetAttribute(gx16_kernel,  cudaFuncAttributeMaxDynamicSharedMemorySize, GX_SMEM);
    cudaFuncSetAttribute(lstm_kernel,  cudaFuncAttributeMaxDynamicSharedMemorySize, LSTM_SMEM);

    pack_kernel<<<512, 256>>>(a_whh, c_whh);

    mlp16_kernel<<<1024, 256, MLP_SMEM>>>(state, a_w1, a_b1, a_w2, a_b2, 0);
    mlp16_kernel<<<1024, 256, MLP_SMEM>>>(state, c_w1, c_b1, c_w2, c_b2, 1);

    dim3 gxg(1024, 4);
    gx16_kernel<<<gxg, 256, GX_SMEM>>>(a_wih, a_bih, a_bhh, 0);
    gx16_kernel<<<gxg, 256, GX_SMEM>>>(c_wih, c_bih, c_bhh, 1);

    lstm_kernel<<<128, 256, LSTM_SMEM>>>(dones);

    heads_kernel<<<NROW / 8, 256>>>(mean_w, mean_b, lstd_w, lstd_b,
                                    val_w, val_b, (float*)d_out);
}

// round 5
// speedup vs baseline: 2.3406x; 1.4760x over previous
#include <cuda_runtime.h>
#include <cuda_fp16.h>

// Problem dims
#define TT 512
#define BB 256
#define SS 64
#define HH 128
#define NROW (TT*BB)          // 131072

// ---------------- scratch (device globals; no allocation allowed) ----------------
__device__ __half g_f2h[(size_t)2 * NROW * HH];      // post-MLP features fp16 (67MB)
__device__ __half g_gxh[(size_t)2 * NROW * 512];     // gx fp16 (268MB)
__device__ __half g_hh [(size_t)2 * NROW * HH];      // LSTM hidden outputs fp16 (67MB)

// ---------------- helpers ----------------
__device__ __forceinline__ float tanh_t(float x) {
    float y; asm("tanh.approx.f32 %0, %1;" : "=f"(y) : "f"(x)); return y;
}
__device__ __forceinline__ float sig_t(float x) {
    return fmaf(tanh_t(x * 0.5f), 0.5f, 0.5f);
}
__device__ __forceinline__ void mma16816(float* c, const unsigned* a, const unsigned* b) {
    asm volatile(
        "mma.sync.aligned.m16n8k16.row.col.f32.f16.f16.f32 "
        "{%0,%1,%2,%3}, {%4,%5,%6,%7}, {%8,%9}, {%0,%1,%2,%3};\n"
        : "+f"(c[0]), "+f"(c[1]), "+f"(c[2]), "+f"(c[3])
        : "r"(a[0]), "r"(a[1]), "r"(a[2]), "r"(a[3]), "r"(b[0]), "r"(b[1]));
}
__device__ __forceinline__ void ldsm4(unsigned* d, const __half* p) {
    unsigned addr = (unsigned)__cvta_generic_to_shared(p);
    asm volatile("ldmatrix.sync.aligned.m8n8.x4.shared.b16 {%0,%1,%2,%3}, [%4];\n"
                 : "=r"(d[0]), "=r"(d[1]), "=r"(d[2]), "=r"(d[3]) : "r"(addr));
}

// =====================================================================
// Tensor-core fused MLP: f2 = relu(relu(X@W1.T+b1)@W2.T+b2)  (fp16 HMMA)
// =====================================================================
#define XS_STR 72
#define MH_STR 136
#define MLP_SMEM (2048 + (128*XS_STR + 128*XS_STR + 128*MH_STR + 128*MH_STR) * 2)

__global__ void __launch_bounds__(256) mlp16_kernel(
    const float* __restrict__ x,
    const float* __restrict__ w1, const float* __restrict__ b1,
    const float* __restrict__ w2, const float* __restrict__ b2, int net)
{
    extern __shared__ __align__(16) char smraw[];
    float* bs1 = (float*)smraw;            // 128
    float* bs2 = bs1 + 128;                // 128
    __half* Xs  = (__half*)(smraw + 2048);
    __half* W1s = Xs  + 128 * XS_STR;
    __half* W2s = W1s + 128 * XS_STR;
    __half* C1s = W2s + 128 * MH_STR;

    int tid = threadIdx.x;
    size_t rowbase = (size_t)blockIdx.x * 128;

    {   // X [128][64]
        const float4* xg = (const float4*)(x + rowbase * SS);
        for (int i = tid; i < 128 * 16; i += 256) {
            int r = i >> 4, c4 = i & 15;
            float4 v = xg[(size_t)r * 16 + c4];
            *(__half2*)&Xs[r * XS_STR + c4 * 4]     = __floats2half2_rn(v.x, v.y);
            *(__half2*)&Xs[r * XS_STR + c4 * 4 + 2] = __floats2half2_rn(v.z, v.w);
        }
    }
    {   // W1 [128][64]
        const float4* wg = (const float4*)w1;
        for (int i = tid; i < 128 * 16; i += 256) {
            int r = i >> 4, c4 = i & 15;
            float4 v = wg[(size_t)r * 16 + c4];
            *(__half2*)&W1s[r * XS_STR + c4 * 4]     = __floats2half2_rn(v.x, v.y);
            *(__half2*)&W1s[r * XS_STR + c4 * 4 + 2] = __floats2half2_rn(v.z, v.w);
        }
    }
    {   // W2 [128][128]
        const float4* wg = (const float4*)w2;
        for (int i = tid; i < 128 * 32; i += 256) {
            int r = i >> 5, c4 = i & 31;
            float4 v = wg[(size_t)r * 32 + c4];
            *(__half2*)&W2s[r * MH_STR + c4 * 4]     = __floats2half2_rn(v.x, v.y);
            *(__half2*)&W2s[r * MH_STR + c4 * 4 + 2] = __floats2half2_rn(v.z, v.w);
        }
    }
    if (tid < 128) { bs1[tid] = __ldg(b1 + tid); bs2[tid] = __ldg(b2 + tid); }
    __syncthreads();

    int wid = tid >> 5, lane = tid & 31;
    int warp_m = wid & 3, warp_n = wid >> 2;
    int m_base = warp_m * 32, n_base = warp_n * 64;

    float acc[2][8][4];

    // stage A: K=64
    #pragma unroll
    for (int mt = 0; mt < 2; mt++)
        #pragma unroll
        for (int nt = 0; nt < 8; nt++)
            #pragma unroll
            for (int q = 0; q < 4; q++) acc[mt][nt][q] = 0.f;

    #pragma unroll
    for (int kt = 0; kt < 4; kt++) {
        int k0 = kt * 16;
        unsigned a[2][4], b[8][2];
        #pragma unroll
        for (int mt = 0; mt < 2; mt++) {
            int r = m_base + mt * 16 + (lane & 15);
            int c = k0 + ((lane >> 4) << 3);
            ldsm4(a[mt], Xs + r * XS_STR + c);
        }
        #pragma unroll
        for (int np = 0; np < 4; np++) {
            int n0 = n_base + np * 16;
            int rr = n0 + ((lane >> 4) << 3) + (lane & 7);
            int cc = k0 + (((lane >> 3) & 1) << 3);
            unsigned t4[4];
            ldsm4(t4, W1s + rr * XS_STR + cc);
            b[np * 2][0] = t4[0]; b[np * 2][1] = t4[1];
            b[np * 2 + 1][0] = t4[2]; b[np * 2 + 1][1] = t4[3];
        }
        #pragma unroll
        for (int mt = 0; mt < 2; mt++)
            #pragma unroll
            for (int nt = 0; nt < 8; nt++)
                mma16816(acc[mt][nt], a[mt], b[nt]);
    }
    #pragma unroll
    for (int mt = 0; mt < 2; mt++) {
        #pragma unroll
        for (int nt = 0; nt < 8; nt++) {
            int r = m_base + mt * 16 + (lane >> 2);
            int c = n_base + nt * 8 + 2 * (lane & 3);
            float v0 = fmaxf(acc[mt][nt][0] + bs1[c], 0.f);
            float v1 = fmaxf(acc[mt][nt][1] + bs1[c + 1], 0.f);
            float v2 = fmaxf(acc[mt][nt][2] + bs1[c], 0.f);
            float v3 = fmaxf(acc[mt][nt][3] + bs1[c + 1], 0.f);
            *(__half2*)&C1s[r * MH_STR + c]       = __floats2half2_rn(v0, v1);
            *(__half2*)&C1s[(r + 8) * MH_STR + c] = __floats2half2_rn(v2, v3);
        }
    }
    __syncthreads();

    // stage B: K=128
    #pragma unroll
    for (int mt = 0; mt < 2; mt++)
        #pragma unroll
        for (int nt = 0; nt < 8; nt++)
            #pragma unroll
            for (int q = 0; q < 4; q++) acc[mt][nt][q] = 0.f;

    #pragma unroll
    for (int kt = 0; kt < 8; kt++) {
        int k0 = kt * 16;
        unsigned a[2][4], b[8][2];
        #pragma unroll
        for (int mt = 0; mt < 2; mt++) {
            int r = m_base + mt * 16 + (lane & 15);
            int c = k0 + ((lane >> 4) << 3);
            ldsm4(a[mt], C1s + r * MH_STR + c);
        }
        #pragma unroll
        for (int np = 0; np < 4; np++) {
            int n0 = n_base + np * 16;
            int rr = n0 + ((lane >> 4) << 3) + (lane & 7);
            int cc = k0 + (((lane >> 3) & 1) << 3);
            unsigned t4[4];
            ldsm4(t4, W2s + rr * MH_STR + cc);
            b[np * 2][0] = t4[0]; b[np * 2][1] = t4[1];
            b[np * 2 + 1][0] = t4[2]; b[np * 2 + 1][1] = t4[3];
        }
        #pragma unroll
        for (int mt = 0; mt < 2; mt++)
            #pragma unroll
            for (int nt = 0; nt < 8; nt++)
                mma16816(acc[mt][nt], a[mt], b[nt]);
    }
    {
        __half* outp = g_f2h + (size_t)net * NROW * HH;
        #pragma unroll
        for (int mt = 0; mt < 2; mt++) {
            #pragma unroll
            for (int nt = 0; nt < 8; nt++) {
                int r = m_base + mt * 16 + (lane >> 2);
                int c = n_base + nt * 8 + 2 * (lane & 3);
                float v0 = fmaxf(acc[mt][nt][0] + bs2[c], 0.f);
                float v1 = fmaxf(acc[mt][nt][1] + bs2[c + 1], 0.f);
                float v2 = fmaxf(acc[mt][nt][2] + bs2[c], 0.f);
                float v3 = fmaxf(acc[mt][nt][3] + bs2[c + 1], 0.f);
                *(__half2*)(outp + (rowbase + r) * (size_t)HH + c) = __floats2half2_rn(v0, v1);
                *(__half2*)(outp + (rowbase + r + 8) * (size_t)HH + c) = __floats2half2_rn(v2, v3);
            }
        }
    }
}

// =====================================================================
// Tensor-core gx GEMM: gx = f2 @ wih.T + (bih+bhh)  (fp16 HMMA)
// =====================================================================
#define GX_SMEM (512 + (128*MH_STR + 128*MH_STR) * 2 + 16)

__global__ void __launch_bounds__(256) gx16_kernel(
    const float* __restrict__ wih,
    const float* __restrict__ bih, const float* __restrict__ bhh, int net)
{
    extern __shared__ __align__(16) char smraw[];
    float* bsum = (float*)smraw;           // 128
    __half* As = (__half*)(smraw + 512 + 16);
    __half* Ws = As + 128 * MH_STR;

    int tid = threadIdx.x;
    size_t rowbase = (size_t)blockIdx.x * 128;
    int chunk = blockIdx.y;                // 0..3

    {   // A tile fp16
        const uint4* ag = (const uint4*)(g_f2h + (size_t)net * NROW * HH + rowbase * HH);
        for (int i = tid; i < 128 * 16; i += 256) {
            int r = i >> 4, c = i & 15;
            *(uint4*)&As[r * MH_STR + c * 8] = ag[(size_t)r * 16 + c];
        }
    }
    {   // W chunk fp32 -> fp16
        const float4* wg = (const float4*)(wih + (size_t)chunk * 128 * 128);
        for (int i = tid; i < 128 * 32; i += 256) {
            int r = i >> 5, c4 = i & 31;
            float4 v = wg[(size_t)r * 32 + c4];
            *(__half2*)&Ws[r * MH_STR + c4 * 4]     = __floats2half2_rn(v.x, v.y);
            *(__half2*)&Ws[r * MH_STR + c4 * 4 + 2] = __floats2half2_rn(v.z, v.w);
        }
    }
    if (tid < 128) bsum[tid] = __ldg(bih + chunk * 128 + tid) + __ldg(bhh + chunk * 128 + tid);
    __syncthreads();

    int wid = tid >> 5, lane = tid & 31;
    int warp_m = wid & 3, warp_n = wid >> 2;
    int m_base = warp_m * 32, n_base = warp_n * 64;

    float acc[2][8][4];
    #pragma unroll
    for (int mt = 0; mt < 2; mt++)
        #pragma unroll
        for (int nt = 0; nt < 8; nt++)
            #pragma unroll
            for (int q = 0; q < 4; q++) acc[mt][nt][q] = 0.f;

    #pragma unroll
    for (int kt = 0; kt < 8; kt++) {
        int k0 = kt * 16;
        unsigned a[2][4], b[8][2];
        #pragma unroll
        for (int mt = 0; mt < 2; mt++) {
            int r = m_base + mt * 16 + (lane & 15);
            int c = k0 + ((lane >> 4) << 3);
            ldsm4(a[mt], As + r * MH_STR + c);
        }
        #pragma unroll
        for (int np = 0; np < 4; np++) {
            int n0 = n_base + np * 16;
            int rr = n0 + ((lane >> 4) << 3) + (lane & 7);
            int cc = k0 + (((lane >> 3) & 1) << 3);
            unsigned t4[4];
            ldsm4(t4, Ws + rr * MH_STR + cc);
            b[np * 2][0] = t4[0]; b[np * 2][1] = t4[1];
            b[np * 2 + 1][0] = t4[2]; b[np * 2 + 1][1] = t4[3];
        }
        #pragma unroll
        for (int mt = 0; mt < 2; mt++)
            #pragma unroll
            for (int nt = 0; nt < 8; nt++)
                mma16816(acc[mt][nt], a[mt], b[nt]);
    }
    {
        __half* outp = g_gxh + (size_t)net * NROW * 512;
        #pragma unroll
        for (int mt = 0; mt < 2; mt++) {
            #pragma unroll
            for (int nt = 0; nt < 8; nt++) {
                int r = m_base + mt * 16 + (lane >> 2);
                int c = n_base + nt * 8 + 2 * (lane & 3);
                int gc = chunk * 128 + c;
                float v0 = acc[mt][nt][0] + bsum[c];
                float v1 = acc[mt][nt][1] + bsum[c + 1];
                float v2 = acc[mt][nt][2] + bsum[c];
                float v3 = acc[mt][nt][3] + bsum[c + 1];
                *(__half2*)(outp + (rowbase + r) * (size_t)512 + gc) = __floats2half2_rn(v0, v1);
                *(__half2*)(outp + (rowbase + r + 8) * (size_t)512 + gc) = __floats2half2_rn(v2, v3);
            }
        }
    }
}

// =====================================================================
// LSTM recurrence on HMMA: 64 persistent CTAs, 8 batch rows each.
// Per step: gates[8x512] = h[8x128] @ whh^T (fp16 mma, M padded to 16),
// + gx tile (double-buffered smem, prefetched), scalar gate epilogue.
// =====================================================================
#define L_WS 0
#define L_HB 139264
#define L_GT 147968
#define L_GX 164608
#define L_HO 180992
#define L_MB 183040
#define LSTM_SMEM 185088

__global__ void __launch_bounds__(256) lstm_mma_kernel(
    const int* __restrict__ dones,
    const float* __restrict__ a_whh, const float* __restrict__ c_whh)
{
    extern __shared__ __align__(16) char sm[];
    __half*  Ws    = (__half*)(sm + L_WS);
    __half*  hbuf  = (__half*)(sm + L_HB);
    float*   gates = (float*)(sm + L_GT);
    __half*  gxs   = (__half*)(sm + L_GX);
    __half*  houts = (__half*)(sm + L_HO);
    unsigned* maskb = (unsigned*)(sm + L_MB);

    int tid = threadIdx.x;
    int net = blockIdx.x >> 5;
    int rb  = (blockIdx.x & 31) << 3;          // first of 8 batch rows
    const float* whh = net ? c_whh : a_whh;

    // load whh fp32 -> fp16 smem, row n (gate-major 0..511), stride 136
    for (int i = tid; i < 512 * 32; i += 256) {
        int n = i >> 5, c4 = i & 31;
        float4 v = ((const float4*)whh)[i];
        *(__half2*)&Ws[n * 136 + c4 * 4]     = __floats2half2_rn(v.x, v.y);
        *(__half2*)&Ws[n * 136 + c4 * 4 + 2] = __floats2half2_rn(v.z, v.w);
    }
    // zero h ping-pong (incl. padding rows 8..15)
    for (int i = tid; i < 2 * 16 * 136; i += 256) hbuf[i] = __float2half(0.f);
    // pack dones bits
    for (int s = tid; s < 512; s += 256) {
        unsigned b = 0;
        #pragma unroll
        for (int r = 0; r < 8; r++) b |= ((unsigned)dones[s * 256 + rb + r] & 1u) << r;
        maskb[s] = b;
    }
    // preload gx for t=0
    {
        const uint4* src = (const uint4*)(g_gxh + (size_t)net * NROW * 512 + (size_t)rb * 512);
        uint4* dst = (uint4*)gxs;
        dst[tid * 2]     = src[tid * 2];
        dst[tid * 2 + 1] = src[tid * 2 + 1];
    }
    __syncthreads();

    int lane = tid & 31, wid = tid >> 5;
    int n0w = wid * 64;
    float cst[4] = {0.f, 0.f, 0.f, 0.f};
    const __half* gxg = g_gxh + (size_t)net * NROW * 512;
    __half* hog = g_hh + (size_t)net * NROW * HH;

    for (int t = 0; t < TT; t++) {
        uint4 p0, p1;
        if (t < TT - 1) {
            const uint4* src = (const uint4*)(gxg + (size_t)(t + 1) * 256 * 512 + (size_t)rb * 512);
            p0 = src[tid * 2];
            p1 = src[tid * 2 + 1];
        }

        const __half* hb = hbuf + (t & 1) * (16 * 136);
        unsigned A[8][4];
        #pragma unroll
        for (int kt = 0; kt < 8; kt++)
            ldsm4(A[kt], hb + (lane & 15) * 136 + kt * 16 + ((lane >> 4) << 3));

        float acc[8][4];
        #pragma unroll
        for (int nt = 0; nt < 8; nt++) {
            acc[nt][0] = acc[nt][1] = acc[nt][2] = acc[nt][3] = 0.f;
        }

        #pragma unroll
        for (int kt = 0; kt < 8; kt++) {
            int k0 = kt * 16;
            unsigned b[8][2];
            #pragma unroll
            for (int np = 0; np < 4; np++) {
                int rr = n0w + np * 16 + ((lane >> 4) << 3) + (lane & 7);
                int cc = k0 + (((lane >> 3) & 1) << 3);
                unsigned t4[4];
                ldsm4(t4, Ws + rr * 136 + cc);
                b[np * 2][0] = t4[0]; b[np * 2][1] = t4[1];
                b[np * 2 + 1][0] = t4[2]; b[np * 2 + 1][1] = t4[3];
            }
            #pragma unroll
            for (int nt = 0; nt < 8; nt++)
                mma16816(acc[nt], A[kt], b[nt]);
        }

        // epilogue A: add gx, store fp32 pre-activations
        {
            const __half* gxcur = gxs + (t & 1) * (8 * 512);
            int row = lane >> 2;
            #pragma unroll
            for (int nt = 0; nt < 8; nt++) {
                int n = n0w + nt * 8 + 2 * (lane & 3);
                float2 g = __half22float2(*(const __half2*)(gxcur + row * 512 + n));
                *(float2*)&gates[row * 520 + n] =
                    make_float2(acc[nt][0] + g.x, acc[nt][1] + g.y);
            }
        }
        __syncthreads();

        // epilogue B: gate nonlinearities, cell update, h outputs
        {
            unsigned bits = maskb[t];
            #pragma unroll
            for (int s = 0; s < 4; s++) {
                int q = tid + 256 * s;
                int row = q >> 7, j = q & 127;
                const float* gr = gates + row * 520 + j;
                float gi = gr[0];
                float gf = gr[128];
                float gg = gr[256];
                float go = gr[384];
                float si = sig_t(gi);
                float sf = sig_t(gf);
                float so = sig_t(go);
                float tg = tanh_t(gg);
                float c2 = sf * cst[s] + si * tg;
                float h2 = so * tanh_t(c2);
                houts[row * 128 + j] = __float2half(h2);
                float m = ((bits >> row) & 1u) ? 0.f : 1.f;
                cst[s] = c2 * m;
                hbuf[((t + 1) & 1) * (16 * 136) + row * 136 + j] = __float2half(h2 * m);
            }
            if (t < TT - 1) {
                uint4* dst = (uint4*)(gxs + ((t + 1) & 1) * (8 * 512));
                dst[tid * 2]     = p0;
                dst[tid * 2 + 1] = p1;
            }
        }
        __syncthreads();

        // coalesced hout store: 8 rows x 128 halves
        {
            uint2 v = ((const uint2*)houts)[tid];
            int r = tid >> 5, j4 = (tid & 31) << 2;
            *(uint2*)(hog + (size_t)(t * 256 + rb + r) * HH + j4) = v;
        }
    }
}

// ---------------- heads: warp per row, shfl reductions (fp16 h) ----------------
__global__ void __launch_bounds__(256) heads_kernel(
    const float* __restrict__ mw, const float* __restrict__ mb,
    const float* __restrict__ lw, const float* __restrict__ lb,
    const float* __restrict__ vw, const float* __restrict__ vb,
    float* __restrict__ out)
{
    __shared__ float ws[17][128];
    __shared__ float bs[17];
    int tid = threadIdx.x;
    for (int i = tid; i < 8 * 128; i += 256) {
        ws[i >> 7][i & 127]       = mw[i];
        ws[8 + (i >> 7)][i & 127] = lw[i];
    }
    for (int i = tid; i < 128; i += 256) ws[16][i] = vw[i];
    if (tid < 8) { bs[tid] = mb[tid]; bs[8 + tid] = lb[tid]; }
    if (tid == 16) bs[16] = vb[0];
    __syncthreads();

    int warp = tid >> 5, lane = tid & 31;
    int row = blockIdx.x * 8 + warp;

    const __half2* ha = (const __half2*)(g_hh + (size_t)row * HH) + lane * 2;
    const __half2* hc = (const __half2*)(g_hh + (size_t)NROW * HH + (size_t)row * HH) + lane * 2;
    float2 a0 = __half22float2(ha[0]);
    float2 a1 = __half22float2(ha[1]);
    float2 c0 = __half22float2(hc[0]);
    float2 c1 = __half22float2(hc[1]);

    float p[17];
    #pragma unroll
    for (int o = 0; o < 16; o++) {
        float4 wv = *(const float4*)(&ws[o][lane * 4]);
        p[o] = a0.x * wv.x + a0.y * wv.y + a1.x * wv.z + a1.y * wv.w;
    }
    {
        float4 wv = *(const float4*)(&ws[16][lane * 4]);
        p[16] = c0.x * wv.x + c0.y * wv.y + c1.x * wv.z + c1.y * wv.w;
    }
    #pragma unroll
    for (int o = 0; o < 17; o++) {
        p[o] += __shfl_xor_sync(0xffffffff, p[o], 16);
        p[o] += __shfl_xor_sync(0xffffffff, p[o], 8);
        p[o] += __shfl_xor_sync(0xffffffff, p[o], 4);
        p[o] += __shfl_xor_sync(0xffffffff, p[o], 2);
        p[o] += __shfl_xor_sync(0xffffffff, p[o], 1);
    }
    if (lane < 8) {
        out[(size_t)row * 8 + lane] = p[lane] + bs[lane];
    } else if (lane < 16) {
        out[(size_t)NROW * 8 + (size_t)row * 8 + (lane - 8)] = __expf(p[lane] + bs[lane]);
    } else if (lane == 16) {
        out[(size_t)NROW * 16 + row] = p[16] + bs[16];
    }
}

// ---------------- launch ----------------
extern "C" void kernel_launch(void* const* d_in, const int* in_sizes, int n_in,
                              void* d_out, int out_size)
{
    const float* state  = (const float*)d_in[0];
    const int*   dones  = (const int*)d_in[1];
    const float* a_w1   = (const float*)d_in[2];
    const float* a_b1   = (const float*)d_in[3];
    const float* a_w2   = (const float*)d_in[4];
    const float* a_b2   = (const float*)d_in[5];
    const float* c_w1   = (const float*)d_in[6];
    const float* c_b1   = (const float*)d_in[7];
    const float* c_w2   = (const float*)d_in[8];
    const float* c_b2   = (const float*)d_in[9];
    const float* a_wih  = (const float*)d_in[10];
    const float* a_whh  = (const float*)d_in[11];
    const float* a_bih  = (const float*)d_in[12];
    const float* a_bhh  = (const float*)d_in[13];
    const float* c_wih  = (const float*)d_in[14];
    const float* c_whh  = (const float*)d_in[15];
    const float* c_bih  = (const float*)d_in[16];
    const float* c_bhh  = (const float*)d_in[17];
    const float* mean_w = (const float*)d_in[18];
    const float* mean_b = (const float*)d_in[19];
    const float* lstd_w = (const float*)d_in[20];
    const float* lstd_b = (const float*)d_in[21];
    const float* val_w  = (const float*)d_in[22];
    const float* val_b  = (const float*)d_in[23];

    cudaFuncSetAttribute(mlp16_kernel,    cudaFuncAttributeMaxDynamicSharedMemorySize, MLP_SMEM);
    cudaFuncSetAttribute(gx16_kernel,     cudaFuncAttributeMaxDynamicSharedMemorySize, GX_SMEM);
    cudaFuncSetAttribute(lstm_mma_kernel, cudaFuncAttributeMaxDynamicSharedMemorySize, LSTM_SMEM);

    mlp16_kernel<<<1024, 256, MLP_SMEM>>>(state, a_w1, a_b1, a_w2, a_b2, 0);
    mlp16_kernel<<<1024, 256, MLP_SMEM>>>(state, c_w1, c_b1, c_w2, c_b2, 1);

    dim3 gxg(1024, 4);
    gx16_kernel<<<gxg, 256, GX_SMEM>>>(a_wih, a_bih, a_bhh, 0);
    gx16_kernel<<<gxg, 256, GX_SMEM>>>(c_wih, c_bih, c_bhh, 1);

    lstm_mma_kernel<<<64, 256, LSTM_SMEM>>>(dones, a_whh, c_whh);

    heads_kernel<<<NROW / 8, 256>>>(mean_w, mean_b, lstd_w, lstd_b,
                                    val_w, val_b, (float*)d_out);
}

// round 6
// speedup vs baseline: 3.1911x; 1.3634x over previous
#include <cuda_runtime.h>
#include <cuda_fp16.h>

// Problem dims
#define TT 512
#define BB 256
#define SS 64
#define HH 128
#define NROW (TT*BB)          // 131072

// ---------------- scratch (device globals; no allocation allowed) ----------------
__device__ __half g_f2h[(size_t)2 * NROW * HH];      // post-MLP features fp16 (67MB)
__device__ __half g_gxh[(size_t)2 * NROW * 512];     // gx fp16 (268MB)
__device__ __half g_hh [(size_t)2 * NROW * HH];      // LSTM hidden outputs fp16 (67MB)
__device__ __half g_wih16[2 * 512 * 128];            // wih packed fp16

// ---------------- helpers ----------------
__device__ __forceinline__ float tanh_t(float x) {
    float y; asm("tanh.approx.f32 %0, %1;" : "=f"(y) : "f"(x)); return y;
}
__device__ __forceinline__ float sig_t(float x) {
    return fmaf(tanh_t(x * 0.5f), 0.5f, 0.5f);
}
__device__ __forceinline__ void mma16816(float* c, const unsigned* a, const unsigned* b) {
    asm volatile(
        "mma.sync.aligned.m16n8k16.row.col.f32.f16.f16.f32 "
        "{%0,%1,%2,%3}, {%4,%5,%6,%7}, {%8,%9}, {%0,%1,%2,%3};\n"
        : "+f"(c[0]), "+f"(c[1]), "+f"(c[2]), "+f"(c[3])
        : "r"(a[0]), "r"(a[1]), "r"(a[2]), "r"(a[3]), "r"(b[0]), "r"(b[1]));
}
__device__ __forceinline__ void ldsm4(unsigned* d, const __half* p) {
    unsigned addr = (unsigned)__cvta_generic_to_shared((void*)p);
    asm volatile("ldmatrix.sync.aligned.m8n8.x4.shared.b16 {%0,%1,%2,%3}, [%4];\n"
                 : "=r"(d[0]), "=r"(d[1]), "=r"(d[2]), "=r"(d[3]) : "r"(addr));
}
__device__ __forceinline__ unsigned smem_u32(const void* p) {
    return (unsigned)__cvta_generic_to_shared((void*)p);
}
__device__ __forceinline__ void cpa16(void* smem_dst, const void* gsrc) {
    unsigned s = smem_u32(smem_dst);
    asm volatile("cp.async.cg.shared.global [%0], [%1], 16;" :: "r"(s), "l"(gsrc));
}
#define CP_COMMIT asm volatile("cp.async.commit_group;" ::: "memory")
#define CP_WAIT0  asm volatile("cp.async.wait_group 0;" ::: "memory")

__device__ __forceinline__ unsigned mapa_u32(unsigned addr, unsigned rank) {
    unsigned r;
    asm("mapa.shared::cluster.u32 %0, %1, %2;" : "=r"(r) : "r"(addr), "r"(rank));
    return r;
}
__device__ __forceinline__ void mbar_wait_acq_cluster(unsigned bar, unsigned parity) {
    asm volatile(
        "{\n\t.reg .pred P;\n"
        "W_%=:\n\t"
        "mbarrier.try_wait.parity.acquire.cluster.shared::cta.b64 P, [%0], %1;\n\t"
        "@P bra.uni D_%=;\n\t"
        "bra.uni W_%=;\n\t"
        "D_%=:\n\t}"
        :: "r"(bar), "r"(parity) : "memory");
}
__device__ __forceinline__ void mbar_arrive_rel_cluster(unsigned rem_bar) {
    asm volatile("mbarrier.arrive.release.cluster.shared::cluster.b64 _, [%0];"
                 :: "r"(rem_bar) : "memory");
}
__device__ __forceinline__ void st_cluster_u32(unsigned addr, unsigned v) {
    asm volatile("st.shared::cluster.b32 [%0], %1;" :: "r"(addr), "r"(v) : "memory");
}

// ---------------- pack wih -> fp16 ----------------
__global__ void pack16_kernel(const float* __restrict__ a_wih, const float* __restrict__ c_wih) {
    int idx = blockIdx.x * blockDim.x + threadIdx.x;
    if (idx >= 2 * 65536) return;
    int net = idx >> 16, r = idx & 65535;
    g_wih16[idx] = __float2half((net ? c_wih : a_wih)[r]);
}

// =====================================================================
// Tensor-core fused MLP (unchanged from R5)
// =====================================================================
#define XS_STR 72
#define MH_STR 136
#define MLP_SMEM (2048 + (128*XS_STR + 128*XS_STR + 128*MH_STR + 128*MH_STR) * 2)

__global__ void __launch_bounds__(256) mlp16_kernel(
    const float* __restrict__ x,
    const float* __restrict__ w1, const float* __restrict__ b1,
    const float* __restrict__ w2, const float* __restrict__ b2, int net)
{
    extern __shared__ __align__(16) char smraw[];
    float* bs1 = (float*)smraw;
    float* bs2 = bs1 + 128;
    __half* Xs  = (__half*)(smraw + 2048);
    __half* W1s = Xs  + 128 * XS_STR;
    __half* W2s = W1s + 128 * XS_STR;
    __half* C1s = W2s + 128 * MH_STR;

    int tid = threadIdx.x;
    size_t rowbase = (size_t)blockIdx.x * 128;

    {
        const float4* xg = (const float4*)(x + rowbase * SS);
        for (int i = tid; i < 128 * 16; i += 256) {
            int r = i >> 4, c4 = i & 15;
            float4 v = xg[(size_t)r * 16 + c4];
            *(__half2*)&Xs[r * XS_STR + c4 * 4]     = __floats2half2_rn(v.x, v.y);
            *(__half2*)&Xs[r * XS_STR + c4 * 4 + 2] = __floats2half2_rn(v.z, v.w);
        }
    }
    {
        const float4* wg = (const float4*)w1;
        for (int i = tid; i < 128 * 16; i += 256) {
            int r = i >> 4, c4 = i & 15;
            float4 v = wg[(size_t)r * 16 + c4];
            *(__half2*)&W1s[r * XS_STR + c4 * 4]     = __floats2half2_rn(v.x, v.y);
            *(__half2*)&W1s[r * XS_STR + c4 * 4 + 2] = __floats2half2_rn(v.z, v.w);
        }
    }
    {
        const float4* wg = (const float4*)w2;
        for (int i = tid; i < 128 * 32; i += 256) {
            int r = i >> 5, c4 = i & 31;
            float4 v = wg[(size_t)r * 32 + c4];
            *(__half2*)&W2s[r * MH_STR + c4 * 4]     = __floats2half2_rn(v.x, v.y);
            *(__half2*)&W2s[r * MH_STR + c4 * 4 + 2] = __floats2half2_rn(v.z, v.w);
        }
    }
    if (tid < 128) { bs1[tid] = __ldg(b1 + tid); bs2[tid] = __ldg(b2 + tid); }
    __syncthreads();

    int wid = tid >> 5, lane = tid & 31;
    int warp_m = wid & 3, warp_n = wid >> 2;
    int m_base = warp_m * 32, n_base = warp_n * 64;

    float acc[2][8][4];

    #pragma unroll
    for (int mt = 0; mt < 2; mt++)
        #pragma unroll
        for (int nt = 0; nt < 8; nt++)
            #pragma unroll
            for (int q = 0; q < 4; q++) acc[mt][nt][q] = 0.f;

    #pragma unroll
    for (int kt = 0; kt < 4; kt++) {
        int k0 = kt * 16;
        unsigned a[2][4], b[8][2];
        #pragma unroll
        for (int mt = 0; mt < 2; mt++) {
            int r = m_base + mt * 16 + (lane & 15);
            int c = k0 + ((lane >> 4) << 3);
            ldsm4(a[mt], Xs + r * XS_STR + c);
        }
        #pragma unroll
        for (int np = 0; np < 4; np++) {
            int n0 = n_base + np * 16;
            int rr = n0 + ((lane >> 4) << 3) + (lane & 7);
            int cc = k0 + (((lane >> 3) & 1) << 3);
            unsigned t4[4];
            ldsm4(t4, W1s + rr * XS_STR + cc);
            b[np * 2][0] = t4[0]; b[np * 2][1] = t4[1];
            b[np * 2 + 1][0] = t4[2]; b[np * 2 + 1][1] = t4[3];
        }
        #pragma unroll
        for (int mt = 0; mt < 2; mt++)
            #pragma unroll
            for (int nt = 0; nt < 8; nt++)
                mma16816(acc[mt][nt], a[mt], b[nt]);
    }
    #pragma unroll
    for (int mt = 0; mt < 2; mt++) {
        #pragma unroll
        for (int nt = 0; nt < 8; nt++) {
            int r = m_base + mt * 16 + (lane >> 2);
            int c = n_base + nt * 8 + 2 * (lane & 3);
            float v0 = fmaxf(acc[mt][nt][0] + bs1[c], 0.f);
            float v1 = fmaxf(acc[mt][nt][1] + bs1[c + 1], 0.f);
            float v2 = fmaxf(acc[mt][nt][2] + bs1[c], 0.f);
            float v3 = fmaxf(acc[mt][nt][3] + bs1[c + 1], 0.f);
            *(__half2*)&C1s[r * MH_STR + c]       = __floats2half2_rn(v0, v1);
            *(__half2*)&C1s[(r + 8) * MH_STR + c] = __floats2half2_rn(v2, v3);
        }
    }
    __syncthreads();

    #pragma unroll
    for (int mt = 0; mt < 2; mt++)
        #pragma unroll
        for (int nt = 0; nt < 8; nt++)
            #pragma unroll
            for (int q = 0; q < 4; q++) acc[mt][nt][q] = 0.f;

    #pragma unroll
    for (int kt = 0; kt < 8; kt++) {
        int k0 = kt * 16;
        unsigned a[2][4], b[8][2];
        #pragma unroll
        for (int mt = 0; mt < 2; mt++) {
            int r = m_base + mt * 16 + (lane & 15);
            int c = k0 + ((lane >> 4) << 3);
            ldsm4(a[mt], C1s + r * MH_STR + c);
        }
        #pragma unroll
        for (int np = 0; np < 4; np++) {
            int n0 = n_base + np * 16;
            int rr = n0 + ((lane >> 4) << 3) + (lane & 7);
            int cc = k0 + (((lane >> 3) & 1) << 3);
            unsigned t4[4];
            ldsm4(t4, W2s + rr * MH_STR + cc);
            b[np * 2][0] = t4[0]; b[np * 2][1] = t4[1];
            b[np * 2 + 1][0] = t4[2]; b[np * 2 + 1][1] = t4[3];
        }
        #pragma unroll
        for (int mt = 0; mt < 2; mt++)
            #pragma unroll
            for (int nt = 0; nt < 8; nt++)
                mma16816(acc[mt][nt], a[mt], b[nt]);
    }
    {
        __half* outp = g_f2h + (size_t)net * NROW * HH;
        #pragma unroll
        for (int mt = 0; mt < 2; mt++) {
            #pragma unroll
            for (int nt = 0; nt < 8; nt++) {
                int r = m_base + mt * 16 + (lane >> 2);
                int c = n_base + nt * 8 + 2 * (lane & 3);
                float v0 = fmaxf(acc[mt][nt][0] + bs2[c], 0.f);
                float v1 = fmaxf(acc[mt][nt][1] + bs2[c + 1], 0.f);
                float v2 = fmaxf(acc[mt][nt][2] + bs2[c], 0.f);
                float v3 = fmaxf(acc[mt][nt][3] + bs2[c + 1], 0.f);
                *(__half2*)(outp + (rowbase + r) * (size_t)HH + c) = __floats2half2_rn(v0, v1);
                *(__half2*)(outp + (rowbase + r + 8) * (size_t)HH + c) = __floats2half2_rn(v2, v3);
            }
        }
    }
}

// =====================================================================
// Fused gx GEMM: one CTA computes a 128-row tile x all 512 cols.
// A tile loaded once (cp.async), A frags hoisted to regs, Ws double-buffered.
// grid (1024, 2): blockIdx.y = net
// =====================================================================
#define GXF_SMEM (106512)

__global__ void __launch_bounds__(256) gxf_kernel(
    const float* __restrict__ a_bih, const float* __restrict__ a_bhh,
    const float* __restrict__ c_bih, const float* __restrict__ c_bhh)
{
    extern __shared__ __align__(16) char smraw[];
    float*  bsum = (float*)smraw;                 // 512 floats
    __half* As   = (__half*)(smraw + 2048);       // 128 x 136
    __half* Wb[2];
    Wb[0] = (__half*)(smraw + 36864);
    Wb[1] = (__half*)(smraw + 71680);

    int tid = threadIdx.x;
    int net = blockIdx.y;
    size_t rowbase = (size_t)blockIdx.x * 128;
    const __half* f2   = g_f2h + (size_t)net * NROW * HH;
    const __half* wsrc = g_wih16 + (size_t)net * 65536;

    // async: A tile + chunk 0 weights
    for (int i = tid; i < 2048; i += 256) {
        int r = i >> 4, c = i & 15;
        cpa16(As + r * 136 + c * 8, f2 + (rowbase + r) * HH + c * 8);
    }
    for (int i = tid; i < 2048; i += 256) {
        int r = i >> 4, c = i & 15;
        cpa16(Wb[0] + r * 136 + c * 8, wsrc + r * 128 + c * 8);
    }
    CP_COMMIT;
    {
        const float* bih = net ? c_bih : a_bih;
        const float* bhh = net ? c_bhh : a_bhh;
        for (int i = tid; i < 512; i += 256) bsum[i] = __ldg(bih + i) + __ldg(bhh + i);
    }
    CP_WAIT0;
    __syncthreads();

    int wid = tid >> 5, lane = tid & 31;
    int warp_m = wid & 3, warp_n = wid >> 2;
    int m_base = warp_m * 32, n_base = warp_n * 64;

    // hoist A fragments (invariant across chunks)
    unsigned a[8][2][4];
    #pragma unroll
    for (int kt = 0; kt < 8; kt++)
        #pragma unroll
        for (int mt = 0; mt < 2; mt++) {
            int r = m_base + mt * 16 + (lane & 15);
            int c = kt * 16 + ((lane >> 4) << 3);
            ldsm4(a[kt][mt], As + r * 136 + c);
        }

    __half* outp = g_gxh + (size_t)net * NROW * 512;

    #pragma unroll
    for (int ch = 0; ch < 4; ch++) {
        if (ch < 3) {
            const __half* src = wsrc + (ch + 1) * 128 * 128;
            __half* dst = Wb[(ch + 1) & 1];
            for (int i = tid; i < 2048; i += 256) {
                int r = i >> 4, c = i & 15;
                cpa16(dst + r * 136 + c * 8, src + r * 128 + c * 8);
            }
            CP_COMMIT;
        }
        const __half* Ws = Wb[ch & 1];

        float acc[2][8][4];
        #pragma unroll
        for (int mt = 0; mt < 2; mt++)
            #pragma unroll
            for (int nt = 0; nt < 8; nt++)
                #pragma unroll
                for (int q = 0; q < 4; q++) acc[mt][nt][q] = 0.f;

        #pragma unroll
        for (int kt = 0; kt < 8; kt++) {
            int k0 = kt * 16;
            unsigned b[8][2];
            #pragma unroll
            for (int np = 0; np < 4; np++) {
                int n0 = n_base + np * 16;
                int rr = n0 + ((lane >> 4) << 3) + (lane & 7);
                int cc = k0 + (((lane >> 3) & 1) << 3);
                unsigned t4[4];
                ldsm4(t4, Ws + rr * 136 + cc);
                b[np * 2][0] = t4[0]; b[np * 2][1] = t4[1];
                b[np * 2 + 1][0] = t4[2]; b[np * 2 + 1][1] = t4[3];
            }
            #pragma unroll
            for (int mt = 0; mt < 2; mt++)
                #pragma unroll
                for (int nt = 0; nt < 8; nt++)
                    mma16816(acc[mt][nt], a[kt][mt], b[nt]);
        }
        // epilogue for this chunk
        #pragma unroll
        for (int mt = 0; mt < 2; mt++) {
            #pragma unroll
            for (int nt = 0; nt < 8; nt++) {
                int r = m_base + mt * 16 + (lane >> 2);
                int c = n_base + nt * 8 + 2 * (lane & 3);
                int gc = ch * 128 + c;
                float v0 = acc[mt][nt][0] + bsum[gc];
                float v1 = acc[mt][nt][1] + bsum[gc + 1];
                float v2 = acc[mt][nt][2] + bsum[gc];
                float v3 = acc[mt][nt][3] + bsum[gc + 1];
                *(__half2*)(outp + (rowbase + r) * (size_t)512 + gc) = __floats2half2_rn(v0, v1);
                *(__half2*)(outp + (rowbase + r + 8) * (size_t)512 + gc) = __floats2half2_rn(v2, v3);
            }
        }
        if (ch < 3) {
            CP_WAIT0;
            __syncthreads();
        }
    }
}

// =====================================================================
// LSTM recurrence, cluster-pair j-split:
// grid 128, clusters of 2. Each CTA: 8 batch rows x 64 hidden cols.
// Ws rows permuted to n = gate*64 + jl (jl local col), K = 128.
// h exchange via DSMEM push + mbarrier (release/acquire, cluster scope).
// smem layout (bytes):
//   Ws    [256][136] half   0      .. 69632
//   hbuf[2][16][136] half   69632  .. 78336  (rows 8-15 zero)
//   gates [8][264]  float   78336  .. 86784
//   gxs [2][8][256]  half   86784  .. 94976
//   houts [8][64]   half    94976  .. 96000
//   maskb [512]     uint    96000  .. 98048
//   mbars [2]       u64     98048  .. 98064
// =====================================================================
#define LW_WS  0
#define LW_HB  69632
#define LW_GT  78336
#define LW_GX  86784
#define LW_HO  94976
#define LW_MB  96000
#define LW_BAR 98048
#define LSTM_SMEM 98080

__global__ void __launch_bounds__(256) __cluster_dims__(2, 1, 1)
lstm_cluster_kernel(const int* __restrict__ dones,
                    const float* __restrict__ a_whh, const float* __restrict__ c_whh)
{
    extern __shared__ __align__(16) char sm[];
    __half*   Ws    = (__half*)(sm + LW_WS);
    __half*   hbuf  = (__half*)(sm + LW_HB);
    float*    gates = (float*)(sm + LW_GT);
    __half*   gxs   = (__half*)(sm + LW_GX);
    __half*   houts = (__half*)(sm + LW_HO);
    unsigned* maskb = (unsigned*)(sm + LW_MB);

    int tid = threadIdx.x;
    int bx  = blockIdx.x;
    int net = bx >> 6;
    int rowgroup = (bx >> 1) & 31;
    int rb = rowgroup << 3;                       // first of 8 batch rows
    unsigned rank;
    asm("mov.u32 %0, %%cluster_ctarank;" : "=r"(rank));
    unsigned peer = rank ^ 1u;
    int jbase = (int)rank * 64;
    const float* whh = net ? c_whh : a_whh;

    // ---- load permuted whh rows: Ws row n = g*64+jl <- whh row g*128+jbase+jl ----
    for (int i = tid; i < 256 * 32; i += 256) {
        int n = i >> 5, c4 = i & 31;
        int orig = ((n >> 6) << 7) + jbase + (n & 63);
        float4 v = ((const float4*)whh)[orig * 32 + c4];
        *(__half2*)&Ws[n * 136 + c4 * 4]     = __floats2half2_rn(v.x, v.y);
        *(__half2*)&Ws[n * 136 + c4 * 4 + 2] = __floats2half2_rn(v.z, v.w);
    }
    for (int i = tid; i < 2 * 16 * 136; i += 256) hbuf[i] = __float2half(0.f);
    for (int s = tid; s < 512; s += 256) {
        unsigned b = 0;
        #pragma unroll
        for (int r = 0; r < 8; r++) b |= ((unsigned)dones[s * 256 + rb + r] & 1u) << r;
        maskb[s] = b;
    }
    const __half* gxg = g_gxh + (size_t)net * NROW * 512;
    // preload gx for t=0 (each CTA: its 4 gate-segments of 64 per row)
    {
        int row = tid >> 5, rem = tid & 31, seg = rem >> 3, q = rem & 7;
        uint4 v = *(const uint4*)(gxg + (size_t)(rb + row) * 512 + seg * 128 + jbase + q * 8);
        ((uint4*)gxs)[row * 32 + seg * 8 + q] = v;
    }
    // mbarriers
    unsigned barL0 = smem_u32(sm + LW_BAR);
    unsigned barL1 = barL0 + 8;
    if (tid == 0) {
        asm volatile("mbarrier.init.shared.b64 [%0], %1;" :: "r"(barL0), "r"(256u));
        asm volatile("mbarrier.init.shared.b64 [%0], %1;" :: "r"(barL1), "r"(256u));
    }
    __syncthreads();
    asm volatile("barrier.cluster.arrive.aligned;" ::: "memory");
    asm volatile("barrier.cluster.wait.aligned;" ::: "memory");

    unsigned remBar[2];
    remBar[0] = mapa_u32(barL0, peer);
    remBar[1] = mapa_u32(barL1, peer);

    int lane = tid & 31, wid = tid >> 5;
    int n0w = wid * 32;

    // hoist B fragments: 8 kt x 4 n-tiles x 2 regs
    unsigned bfr[8][4][2];
    #pragma unroll
    for (int kt = 0; kt < 8; kt++) {
        int k0 = kt * 16;
        #pragma unroll
        for (int np = 0; np < 2; np++) {
            int rr = n0w + np * 16 + ((lane >> 4) << 3) + (lane & 7);
            int cc = k0 + (((lane >> 3) & 1) << 3);
            unsigned t4[4];
            ldsm4(t4, Ws + rr * 136 + cc);
            bfr[kt][np * 2][0] = t4[0]; bfr[kt][np * 2][1] = t4[1];
            bfr[kt][np * 2 + 1][0] = t4[2]; bfr[kt][np * 2 + 1][1] = t4[3];
        }
    }

    // epilogue-B thread mapping: row = tid>>5, jl = 2*(tid&31)
    int erow = tid >> 5;
    int ejl  = (tid & 31) * 2;
    // remote half2 store addresses for each ping-pong buffer
    unsigned remHb[2];
    {
        unsigned base = smem_u32(hbuf);
        #pragma unroll
        for (int buf = 0; buf < 2; buf++) {
            unsigned loc = base + (unsigned)(((buf * 16 + erow) * 136 + jbase + ejl) * 2);
            remHb[buf] = mapa_u32(loc, peer);
        }
    }

    float cstA = 0.f, cstB = 0.f;
    __half* hog = g_hh + (size_t)net * NROW * HH;
    int ph0 = 0, ph1 = 0;

    for (int t = 0; t < TT; t++) {
        bool haveNext = (t < TT - 1);
        uint4 pf;
        if (haveNext) {
            int row = tid >> 5, rem = tid & 31, seg = rem >> 3, q = rem & 7;
            pf = *(const uint4*)(gxg + (size_t)((t + 1) * 256 + rb + row) * 512
                                 + seg * 128 + jbase + q * 8);
        }
        // wait for peer's h-half from step t-1
        if (t > 0) {
            if ((t - 1) & 1) { mbar_wait_acq_cluster(barL1, (unsigned)ph1); ph1 ^= 1; }
            else             { mbar_wait_acq_cluster(barL0, (unsigned)ph0); ph0 ^= 1; }
        }

        // A fragments from full h (128 cols)
        const __half* hb = hbuf + (t & 1) * (16 * 136);
        unsigned A[8][4];
        #pragma unroll
        for (int kt = 0; kt < 8; kt++)
            ldsm4(A[kt], hb + (lane & 15) * 136 + kt * 16 + ((lane >> 4) << 3));

        float acc[4][4];
        #pragma unroll
        for (int nt = 0; nt < 4; nt++)
            #pragma unroll
            for (int q = 0; q < 4; q++) acc[nt][q] = 0.f;

        #pragma unroll
        for (int kt = 0; kt < 8; kt++)
            #pragma unroll
            for (int nt = 0; nt < 4; nt++)
                mma16816(acc[nt], A[kt], bfr[kt][nt]);

        // epilogue A: + gx -> fp32 gates (valid rows 0-7 in acc[.][0..1])
        {
            const __half* gxcur = gxs + (t & 1) * (8 * 256);
            int row = lane >> 2;
            #pragma unroll
            for (int nt = 0; nt < 4; nt++) {
                int n = n0w + nt * 8 + 2 * (lane & 3);
                float2 g = __half22float2(*(const __half2*)(gxcur + row * 256 + n));
                *(float2*)&gates[row * 264 + n] =
                    make_float2(acc[nt][0] + g.x, acc[nt][1] + g.y);
            }
        }
        __syncthreads();

        // epilogue B: 2 adjacent cols per thread
        {
            unsigned bits = maskb[t];
            const float* gr = gates + erow * 264 + ejl;
            float2 fi = *(const float2*)(gr);
            float2 ff = *(const float2*)(gr + 64);
            float2 fg = *(const float2*)(gr + 128);
            float2 fo = *(const float2*)(gr + 192);
            float siA = sig_t(fi.x), siB = sig_t(fi.y);
            float sfA = sig_t(ff.x), sfB = sig_t(ff.y);
            float tgA = tanh_t(fg.x), tgB = tanh_t(fg.y);
            float soA = sig_t(fo.x), soB = sig_t(fo.y);
            float c2A = sfA * cstA + siA * tgA;
            float c2B = sfB * cstB + siB * tgB;
            float h2A = soA * tanh_t(c2A);
            float h2B = soB * tanh_t(c2B);
            *(__half2*)&houts[erow * 64 + ejl] = __floats2half2_rn(h2A, h2B);
            float m = ((bits >> erow) & 1u) ? 0.f : 1.f;
            cstA = c2A * m;
            cstB = c2B * m;
            if (haveNext) {
                int nb = (t + 1) & 1;
                __half2 hm = __floats2half2_rn(h2A * m, h2B * m);
                *(__half2*)&hbuf[(nb * 16 + erow) * 136 + jbase + ejl] = hm;
                st_cluster_u32(remHb[nb], *(unsigned*)&hm);
                // store prefetched gx for next step
                ((uint4*)(gxs + nb * (8 * 256)))[(tid >> 5) * 32 + ((tid & 31) >> 3) * 8 + (tid & 7)] = pf;
                // release-arrive on peer's barrier for this step
                mbar_arrive_rel_cluster(remBar[t & 1]);
            }
        }
        __syncthreads();

        // coalesced hout store: 8 rows x 64 halves (this CTA's j-half)
        if (tid < 64) {
            int r = tid >> 3, q = tid & 7;
            uint4 v = *(const uint4*)(houts + r * 64 + q * 8);
            *(uint4*)(hog + (size_t)(t * 256 + rb + r) * HH + jbase + q * 8) = v;
        }
    }

    asm volatile("barrier.cluster.arrive.aligned;" ::: "memory");
    asm volatile("barrier.cluster.wait.aligned;" ::: "memory");
}

// ---------------- heads: warp per row, shfl reductions (fp16 h) ----------------
__global__ void __launch_bounds__(256) heads_kernel(
    const float* __restrict__ mw, const float* __restrict__ mb,
    const float* __restrict__ lw, const float* __restrict__ lb,
    const float* __restrict__ vw, const float* __restrict__ vb,
    float* __restrict__ out)
{
    __shared__ float ws[17][128];
    __shared__ float bs[17];
    int tid = threadIdx.x;
    for (int i = tid; i < 8 * 128; i += 256) {
        ws[i >> 7][i & 127]       = mw[i];
        ws[8 + (i >> 7)][i & 127] = lw[i];
    }
    for (int i = tid; i < 128; i += 256) ws[16][i] = vw[i];
    if (tid < 8) { bs[tid] = mb[tid]; bs[8 + tid] = lb[tid]; }
    if (tid == 16) bs[16] = vb[0];
    __syncthreads();

    int warp = tid >> 5, lane = tid & 31;
    int row = blockIdx.x * 8 + warp;

    const __half2* ha = (const __half2*)(g_hh + (size_t)row * HH) + lane * 2;
    const __half2* hc = (const __half2*)(g_hh + (size_t)NROW * HH + (size_t)row * HH) + lane * 2;
    float2 a0 = __half22float2(ha[0]);
    float2 a1 = __half22float2(ha[1]);
    float2 c0 = __half22float2(hc[0]);
    float2 c1 = __half22float2(hc[1]);

    float p[17];
    #pragma unroll
    for (int o = 0; o < 16; o++) {
        float4 wv = *(const float4*)(&ws[o][lane * 4]);
        p[o] = a0.x * wv.x + a0.y * wv.y + a1.x * wv.z + a1.y * wv.w;
    }
    {
        float4 wv = *(const float4*)(&ws[16][lane * 4]);
        p[16] = c0.x * wv.x + c0.y * wv.y + c1.x * wv.z + c1.y * wv.w;
    }
    #pragma unroll
    for (int o = 0; o < 17; o++) {
        p[o] += __shfl_xor_sync(0xffffffff, p[o], 16);
        p[o] += __shfl_xor_sync(0xffffffff, p[o], 8);
        p[o] += __shfl_xor_sync(0xffffffff, p[o], 4);
        p[o] += __shfl_xor_sync(0xffffffff, p[o], 2);
        p[o] += __shfl_xor_sync(0xffffffff, p[o], 1);
    }
    if (lane < 8) {
        out[(size_t)row * 8 + lane] = p[lane] + bs[lane];
    } else if (lane < 16) {
        out[(size_t)NROW * 8 + (size_t)row * 8 + (lane - 8)] = __expf(p[lane] + bs[lane]);
    } else if (lane == 16) {
        out[(size_t)NROW * 16 + row] = p[16] + bs[16];
    }
}

// ---------------- launch ----------------
extern "C" void kernel_launch(void* const* d_in, const int* in_sizes, int n_in,
                              void* d_out, int out_size)
{
    const float* state  = (const float*)d_in[0];
    const int*   dones  = (const int*)d_in[1];
    const float* a_w1   = (const float*)d_in[2];
    const float* a_b1   = (const float*)d_in[3];
    const float* a_w2   = (const float*)d_in[4];
    const float* a_b2   = (const float*)d_in[5];
    const float* c_w1   = (const float*)d_in[6];
    const float* c_b1   = (const float*)d_in[7];
    const float* c_w2   = (const float*)d_in[8];
    const float* c_b2   = (const float*)d_in[9];
    const float* a_wih  = (const float*)d_in[10];
    const float* a_whh  = (const float*)d_in[11];
    const float* a_bih  = (const float*)d_in[12];
    const float* a_bhh  = (const float*)d_in[13];
    const float* c_wih  = (const float*)d_in[14];
    const float* c_whh  = (const float*)d_in[15];
    const float* c_bih  = (const float*)d_in[16];
    const float* c_bhh  = (const float*)d_in[17];
    const float* mean_w = (const float*)d_in[18];
    const float* mean_b = (const float*)d_in[19];
    const float* lstd_w = (const float*)d_in[20];
    const float* lstd_b = (const float*)d_in[21];
    const float* val_w  = (const float*)d_in[22];
    const float* val_b  = (const float*)d_in[23];

    cudaFuncSetAttribute(mlp16_kernel, cudaFuncAttributeMaxDynamicSharedMemorySize, MLP_SMEM);
    cudaFuncSetAttribute(gxf_kernel,   cudaFuncAttributeMaxDynamicSharedMemorySize, GXF_SMEM);
    cudaFuncSetAttribute(lstm_cluster_kernel, cudaFuncAttributeMaxDynamicSharedMemorySize, LSTM_SMEM);

    pack16_kernel<<<512, 256>>>(a_wih, c_wih);

    mlp16_kernel<<<1024, 256, MLP_SMEM>>>(state, a_w1, a_b1, a_w2, a_b2, 0);
    mlp16_kernel<<<1024, 256, MLP_SMEM>>>(state, c_w1, c_b1, c_w2, c_b2, 1);

    dim3 gxg(1024, 2);
    gxf_kernel<<<gxg, 256, GXF_SMEM>>>(a_bih, a_bhh, c_bih, c_bhh);

    lstm_cluster_kernel<<<128, 256, LSTM_SMEM>>>(dones, a_whh, c_whh);

    heads_kernel<<<NROW / 8, 256>>>(mean_w, mean_b, lstd_w, lstd_b,
                                    val_w, val_b, (float*)d_out);
}

// round 7
// speedup vs baseline: 3.4392x; 1.0777x over previous
#include <cuda_runtime.h>
#include <cuda_fp16.h>

// Problem dims
#define TT 512
#define BB 256
#define SS 64
#define HH 128
#define NROW (TT*BB)          // 131072

// ---------------- scratch (device globals; no allocation allowed) ----------------
__device__ __half g_gxh[(size_t)2 * NROW * 512];     // gx fp16 (268MB)
__device__ __half g_hh [(size_t)2 * NROW * HH];      // LSTM hidden outputs fp16 (67MB)
__device__ __half g_wih16[2 * 512 * 128];            // wih packed fp16

// ---------------- helpers ----------------
__device__ __forceinline__ float tanh_t(float x) {
    float y; asm("tanh.approx.f32 %0, %1;" : "=f"(y) : "f"(x)); return y;
}
__device__ __forceinline__ float sig_t(float x) {
    return fmaf(tanh_t(x * 0.5f), 0.5f, 0.5f);
}
__device__ __forceinline__ void mma16816(float* c, const unsigned* a, const unsigned* b) {
    asm volatile(
        "mma.sync.aligned.m16n8k16.row.col.f32.f16.f16.f32 "
        "{%0,%1,%2,%3}, {%4,%5,%6,%7}, {%8,%9}, {%0,%1,%2,%3};\n"
        : "+f"(c[0]), "+f"(c[1]), "+f"(c[2]), "+f"(c[3])
        : "r"(a[0]), "r"(a[1]), "r"(a[2]), "r"(a[3]), "r"(b[0]), "r"(b[1]));
}
__device__ __forceinline__ void ldsm4(unsigned* d, const __half* p) {
    unsigned addr = (unsigned)__cvta_generic_to_shared((void*)p);
    asm volatile("ldmatrix.sync.aligned.m8n8.x4.shared.b16 {%0,%1,%2,%3}, [%4];\n"
                 : "=r"(d[0]), "=r"(d[1]), "=r"(d[2]), "=r"(d[3]) : "r"(addr));
}
__device__ __forceinline__ unsigned smem_u32(const void* p) {
    return (unsigned)__cvta_generic_to_shared((void*)p);
}
__device__ __forceinline__ void cpa16(void* smem_dst, const void* gsrc) {
    unsigned s = smem_u32(smem_dst);
    asm volatile("cp.async.cg.shared.global [%0], [%1], 16;" :: "r"(s), "l"(gsrc));
}
#define CP_COMMIT asm volatile("cp.async.commit_group;" ::: "memory")
#define CP_WAIT0  asm volatile("cp.async.wait_group 0;" ::: "memory")

__device__ __forceinline__ unsigned mapa_u32(unsigned addr, unsigned rank) {
    unsigned r;
    asm("mapa.shared::cluster.u32 %0, %1, %2;" : "=r"(r) : "r"(addr), "r"(rank));
    return r;
}
__device__ __forceinline__ void mbar_wait_acq_cluster(unsigned bar, unsigned parity) {
    asm volatile(
        "{\n\t.reg .pred P;\n"
        "W_%=:\n\t"
        "mbarrier.try_wait.parity.acquire.cluster.shared::cta.b64 P, [%0], %1;\n\t"
        "@P bra.uni D_%=;\n\t"
        "bra.uni W_%=;\n\t"
        "D_%=:\n\t}"
        :: "r"(bar), "r"(parity) : "memory");
}
__device__ __forceinline__ void mbar_arrive_rel_cluster(unsigned rem_bar) {
    asm volatile("mbarrier.arrive.release.cluster.shared::cluster.b64 _, [%0];"
                 :: "r"(rem_bar) : "memory");
}
__device__ __forceinline__ void st_cluster_u32(unsigned addr, unsigned v) {
    asm volatile("st.shared::cluster.b32 [%0], %1;" :: "r"(addr), "r"(v) : "memory");
}

// ---------------- pack wih -> fp16 ----------------
__global__ void pack16_kernel(const float* __restrict__ a_wih, const float* __restrict__ c_wih) {
    int idx = blockIdx.x * blockDim.x + threadIdx.x;
    if (idx >= 2 * 65536) return;
    int net = idx >> 16, r = idx & 65535;
    g_wih16[idx] = __float2half((net ? c_wih : a_wih)[r]);
}

// =====================================================================
// Fused feature kernel: f2 = relu(relu(X@W1.T+b1)@W2.T+b2) then
// gx = f2 @ wih.T + (bih+bhh) — all in one CTA per 128-row tile.
// grid (1024, 2): blockIdx.y = net. smem ~109.5KB -> 2 CTA/SM.
// Reuse: F2s overlays Xs+W1s; gx weight double buffers overlay W2s/C1s.
// =====================================================================
#define XS_STR 72
#define MH_STR 136
#define FG_BS  0
#define FG_XS  3072
#define FG_W1S 21504
#define FG_W2S 39936
#define FG_C1S 74752
#define FG_SMEM 109568

__global__ void __launch_bounds__(256) fg_kernel(
    const float* __restrict__ x,
    const float* __restrict__ a_w1, const float* __restrict__ a_b1,
    const float* __restrict__ a_w2, const float* __restrict__ a_b2,
    const float* __restrict__ c_w1, const float* __restrict__ c_b1,
    const float* __restrict__ c_w2, const float* __restrict__ c_b2,
    const float* __restrict__ a_bih, const float* __restrict__ a_bhh,
    const float* __restrict__ c_bih, const float* __restrict__ c_bhh)
{
    extern __shared__ __align__(16) char smraw[];
    float*  bs1  = (float*)(smraw + FG_BS);        // 128
    float*  bs2  = bs1 + 128;                      // 128
    float*  bsum = bs2 + 128;                      // 512
    __half* Xs   = (__half*)(smraw + FG_XS);       // stride 72
    __half* W1s  = (__half*)(smraw + FG_W1S);      // stride 72
    __half* W2s  = (__half*)(smraw + FG_W2S);      // stride 136
    __half* C1s  = (__half*)(smraw + FG_C1S);      // stride 136
    __half* F2s  = (__half*)(smraw + FG_XS);       // stride 136 (overlays Xs+W1s)
    __half* Wb[2]; Wb[0] = W2s; Wb[1] = C1s;

    int tid = threadIdx.x;
    int net = blockIdx.y;
    size_t rowbase = (size_t)blockIdx.x * 128;

    const float* w1 = net ? c_w1 : a_w1;
    const float* b1 = net ? c_b1 : a_b1;
    const float* w2 = net ? c_w2 : a_w2;
    const float* b2 = net ? c_b2 : a_b2;
    const float* bih = net ? c_bih : a_bih;
    const float* bhh = net ? c_bhh : a_bhh;

    {   // X [128][64]
        const float4* xg = (const float4*)(x + rowbase * SS);
        for (int i = tid; i < 128 * 16; i += 256) {
            int r = i >> 4, c4 = i & 15;
            float4 v = xg[(size_t)r * 16 + c4];
            *(__half2*)&Xs[r * XS_STR + c4 * 4]     = __floats2half2_rn(v.x, v.y);
            *(__half2*)&Xs[r * XS_STR + c4 * 4 + 2] = __floats2half2_rn(v.z, v.w);
        }
    }
    {   // W1 [128][64]
        const float4* wg = (const float4*)w1;
        for (int i = tid; i < 128 * 16; i += 256) {
            int r = i >> 4, c4 = i & 15;
            float4 v = wg[(size_t)r * 16 + c4];
            *(__half2*)&W1s[r * XS_STR + c4 * 4]     = __floats2half2_rn(v.x, v.y);
            *(__half2*)&W1s[r * XS_STR + c4 * 4 + 2] = __floats2half2_rn(v.z, v.w);
        }
    }
    {   // W2 [128][128]
        const float4* wg = (const float4*)w2;
        for (int i = tid; i < 128 * 32; i += 256) {
            int r = i >> 5, c4 = i & 31;
            float4 v = wg[(size_t)r * 32 + c4];
            *(__half2*)&W2s[r * MH_STR + c4 * 4]     = __floats2half2_rn(v.x, v.y);
            *(__half2*)&W2s[r * MH_STR + c4 * 4 + 2] = __floats2half2_rn(v.z, v.w);
        }
    }
    if (tid < 128) { bs1[tid] = __ldg(b1 + tid); bs2[tid] = __ldg(b2 + tid); }
    for (int i = tid; i < 512; i += 256) bsum[i] = __ldg(bih + i) + __ldg(bhh + i);
    __syncthreads();

    int wid = tid >> 5, lane = tid & 31;
    int warp_m = wid & 3, warp_n = wid >> 2;
    int m_base = warp_m * 32, n_base = warp_n * 64;

    float acc[2][8][4];

    // -------- stage A: C1 = relu(X @ W1.T + b1), K=64 --------
    #pragma unroll
    for (int mt = 0; mt < 2; mt++)
        #pragma unroll
        for (int nt = 0; nt < 8; nt++)
            #pragma unroll
            for (int q = 0; q < 4; q++) acc[mt][nt][q] = 0.f;

    #pragma unroll
    for (int kt = 0; kt < 4; kt++) {
        int k0 = kt * 16;
        unsigned a[2][4], b[8][2];
        #pragma unroll
        for (int mt = 0; mt < 2; mt++) {
            int r = m_base + mt * 16 + (lane & 15);
            int c = k0 + ((lane >> 4) << 3);
            ldsm4(a[mt], Xs + r * XS_STR + c);
        }
        #pragma unroll
        for (int np = 0; np < 4; np++) {
            int n0 = n_base + np * 16;
            int rr = n0 + ((lane >> 4) << 3) + (lane & 7);
            int cc = k0 + (((lane >> 3) & 1) << 3);
            unsigned t4[4];
            ldsm4(t4, W1s + rr * XS_STR + cc);
            b[np * 2][0] = t4[0]; b[np * 2][1] = t4[1];
            b[np * 2 + 1][0] = t4[2]; b[np * 2 + 1][1] = t4[3];
        }
        #pragma unroll
        for (int mt = 0; mt < 2; mt++)
            #pragma unroll
            for (int nt = 0; nt < 8; nt++)
                mma16816(acc[mt][nt], a[mt], b[nt]);
    }
    #pragma unroll
    for (int mt = 0; mt < 2; mt++) {
        #pragma unroll
        for (int nt = 0; nt < 8; nt++) {
            int r = m_base + mt * 16 + (lane >> 2);
            int c = n_base + nt * 8 + 2 * (lane & 3);
            float v0 = fmaxf(acc[mt][nt][0] + bs1[c], 0.f);
            float v1 = fmaxf(acc[mt][nt][1] + bs1[c + 1], 0.f);
            float v2 = fmaxf(acc[mt][nt][2] + bs1[c], 0.f);
            float v3 = fmaxf(acc[mt][nt][3] + bs1[c + 1], 0.f);
            *(__half2*)&C1s[r * MH_STR + c]       = __floats2half2_rn(v0, v1);
            *(__half2*)&C1s[(r + 8) * MH_STR + c] = __floats2half2_rn(v2, v3);
        }
    }
    __syncthreads();

    // -------- stage B: F2 = relu(C1 @ W2.T + b2), K=128 --------
    #pragma unroll
    for (int mt = 0; mt < 2; mt++)
        #pragma unroll
        for (int nt = 0; nt < 8; nt++)
            #pragma unroll
            for (int q = 0; q < 4; q++) acc[mt][nt][q] = 0.f;

    #pragma unroll
    for (int kt = 0; kt < 8; kt++) {
        int k0 = kt * 16;
        unsigned a[2][4], b[8][2];
        #pragma unroll
        for (int mt = 0; mt < 2; mt++) {
            int r = m_base + mt * 16 + (lane & 15);
            int c = k0 + ((lane >> 4) << 3);
            ldsm4(a[mt], C1s + r * MH_STR + c);
        }
        #pragma unroll
        for (int np = 0; np < 4; np++) {
            int n0 = n_base + np * 16;
            int rr = n0 + ((lane >> 4) << 3) + (lane & 7);
            int cc = k0 + (((lane >> 3) & 1) << 3);
            unsigned t4[4];
            ldsm4(t4, W2s + rr * MH_STR + cc);
            b[np * 2][0] = t4[0]; b[np * 2][1] = t4[1];
            b[np * 2 + 1][0] = t4[2]; b[np * 2 + 1][1] = t4[3];
        }
        #pragma unroll
        for (int mt = 0; mt < 2; mt++)
            #pragma unroll
            for (int nt = 0; nt < 8; nt++)
                mma16816(acc[mt][nt], a[mt], b[nt]);
    }
    // epilogue B -> F2s (smem, overlays Xs/W1s — dead after stage A/B barriers)
    #pragma unroll
    for (int mt = 0; mt < 2; mt++) {
        #pragma unroll
        for (int nt = 0; nt < 8; nt++) {
            int r = m_base + mt * 16 + (lane >> 2);
            int c = n_base + nt * 8 + 2 * (lane & 3);
            float v0 = fmaxf(acc[mt][nt][0] + bs2[c], 0.f);
            float v1 = fmaxf(acc[mt][nt][1] + bs2[c + 1], 0.f);
            float v2 = fmaxf(acc[mt][nt][2] + bs2[c], 0.f);
            float v3 = fmaxf(acc[mt][nt][3] + bs2[c + 1], 0.f);
            *(__half2*)&F2s[r * MH_STR + c]       = __floats2half2_rn(v0, v1);
            *(__half2*)&F2s[(r + 8) * MH_STR + c] = __floats2half2_rn(v2, v3);
        }
    }
    __syncthreads();   // F2s complete; W2s/C1s reads complete -> reuse as Wb

    // -------- gx phase: hoist A frags, loop 4 weight chunks --------
    const __half* wsrc = g_wih16 + (size_t)net * 65536;

    unsigned afr[8][2][4];
    #pragma unroll
    for (int kt = 0; kt < 8; kt++)
        #pragma unroll
        for (int mt = 0; mt < 2; mt++) {
            int r = m_base + mt * 16 + (lane & 15);
            int c = kt * 16 + ((lane >> 4) << 3);
            ldsm4(afr[kt][mt], F2s + r * MH_STR + c);
        }
    // chunk 0 weights
    for (int i = tid; i < 2048; i += 256) {
        int r = i >> 4, c = i & 15;
        cpa16(Wb[0] + r * MH_STR + c * 8, wsrc + r * 128 + c * 8);
    }
    CP_COMMIT;
    CP_WAIT0;
    __syncthreads();

    __half* outp = g_gxh + (size_t)net * NROW * 512;

    #pragma unroll
    for (int ch = 0; ch < 4; ch++) {
        if (ch < 3) {
            const __half* src = wsrc + (ch + 1) * 128 * 128;
            __half* dst = Wb[(ch + 1) & 1];
            for (int i = tid; i < 2048; i += 256) {
                int r = i >> 4, c = i & 15;
                cpa16(dst + r * MH_STR + c * 8, src + r * 128 + c * 8);
            }
            CP_COMMIT;
        }
        const __half* Ws = Wb[ch & 1];

        #pragma unroll
        for (int mt = 0; mt < 2; mt++)
            #pragma unroll
            for (int nt = 0; nt < 8; nt++)
                #pragma unroll
                for (int q = 0; q < 4; q++) acc[mt][nt][q] = 0.f;

        #pragma unroll
        for (int kt = 0; kt < 8; kt++) {
            int k0 = kt * 16;
            unsigned b[8][2];
            #pragma unroll
            for (int np = 0; np < 4; np++) {
                int n0 = n_base + np * 16;
                int rr = n0 + ((lane >> 4) << 3) + (lane & 7);
                int cc = k0 + (((lane >> 3) & 1) << 3);
                unsigned t4[4];
                ldsm4(t4, Ws + rr * MH_STR + cc);
                b[np * 2][0] = t4[0]; b[np * 2][1] = t4[1];
                b[np * 2 + 1][0] = t4[2]; b[np * 2 + 1][1] = t4[3];
            }
            #pragma unroll
            for (int mt = 0; mt < 2; mt++)
                #pragma unroll
                for (int nt = 0; nt < 8; nt++)
                    mma16816(acc[mt][nt], afr[kt][mt], b[nt]);
        }
        #pragma unroll
        for (int mt = 0; mt < 2; mt++) {
            #pragma unroll
            for (int nt = 0; nt < 8; nt++) {
                int r = m_base + mt * 16 + (lane >> 2);
                int c = n_base + nt * 8 + 2 * (lane & 3);
                int gc = ch * 128 + c;
                float v0 = acc[mt][nt][0] + bsum[gc];
                float v1 = acc[mt][nt][1] + bsum[gc + 1];
                float v2 = acc[mt][nt][2] + bsum[gc];
                float v3 = acc[mt][nt][3] + bsum[gc + 1];
                *(__half2*)(outp + (rowbase + r) * (size_t)512 + gc) = __floats2half2_rn(v0, v1);
                *(__half2*)(outp + (rowbase + r + 8) * (size_t)512 + gc) = __floats2half2_rn(v2, v3);
            }
        }
        if (ch < 3) {
            CP_WAIT0;
            __syncthreads();
        }
    }
}

// =====================================================================
// LSTM recurrence, cluster-pair j-split, gate-interleaved Ws:
// Ws row n <- whh row g*128 + jbase + jl, where g=(n>>3)&3, jl=8*(n>>5)+(n&7).
// Warp w's 32 output cols = gates {i,f,g,o} x jl in [8w, 8w+8) => the whole
// cell update lives in one thread's registers. One __syncthreads per step.
// smem (bytes):
//   Ws    [256][136] half   0     .. 69632
//   hbuf[2][16][136] half   69632 .. 78336  (rows 8-15 zero)
//   gxs [2][8][264]  half   78336 .. 86784  (264-stride pad: conflict-free LDS)
//   maskb [512]     uint    86784 .. 88832
//   mbars [2]       u64     88832 .. 88848
// =====================================================================
#define LW_WS  0
#define LW_HB  69632
#define LW_GX  78336
#define LW_MB  86784
#define LW_BAR 88832
#define LSTM_SMEM 88864

__global__ void __launch_bounds__(256) __cluster_dims__(2, 1, 1)
lstm_cluster_kernel(const int* __restrict__ dones,
                    const float* __restrict__ a_whh, const float* __restrict__ c_whh)
{
    extern __shared__ __align__(16) char sm[];
    __half*   Ws    = (__half*)(sm + LW_WS);
    __half*   hbuf  = (__half*)(sm + LW_HB);
    __half*   gxs   = (__half*)(sm + LW_GX);
    unsigned* maskb = (unsigned*)(sm + LW_MB);

    int tid = threadIdx.x;
    int bx  = blockIdx.x;
    int net = bx >> 6;
    int rowgroup = (bx >> 1) & 31;
    int rb = rowgroup << 3;                       // first of 8 batch rows
    unsigned rank;
    asm("mov.u32 %0, %%cluster_ctarank;" : "=r"(rank));
    unsigned peer = rank ^ 1u;
    int jbase = (int)rank * 64;
    const float* whh = net ? c_whh : a_whh;

    // ---- load gate-interleaved whh rows ----
    for (int i = tid; i < 256 * 32; i += 256) {
        int n = i >> 5, c4 = i & 31;
        int g  = (n >> 3) & 3;
        int jl = ((n >> 5) << 3) + (n & 7);
        int orig = g * 128 + jbase + jl;
        float4 v = ((const float4*)whh)[orig * 32 + c4];
        *(__half2*)&Ws[n * 136 + c4 * 4]     = __floats2half2_rn(v.x, v.y);
        *(__half2*)&Ws[n * 136 + c4 * 4 + 2] = __floats2half2_rn(v.z, v.w);
    }
    for (int i = tid; i < 2 * 16 * 136; i += 256) hbuf[i] = __float2half(0.f);
    for (int s = tid; s < 512; s += 256) {
        unsigned b = 0;
        #pragma unroll
        for (int r = 0; r < 8; r++) b |= ((unsigned)dones[s * 256 + rb + r] & 1u) << r;
        maskb[s] = b;
    }
    const __half* gxg = g_gxh + (size_t)net * NROW * 512;
    // preload gx t=0: thread -> (row=tid>>5, seg=(tid&31)>>3, q=tid&7)
    {
        int row = tid >> 5, rem = tid & 31, seg = rem >> 3, q = rem & 7;
        uint4 v = *(const uint4*)(gxg + (size_t)(rb + row) * 512 + seg * 128 + jbase + q * 8);
        ((uint4*)gxs)[33 * row + 8 * seg + q] = v;
    }
    // mbarriers
    unsigned barL0 = smem_u32(sm + LW_BAR);
    unsigned barL1 = barL0 + 8;
    if (tid == 0) {
        asm volatile("mbarrier.init.shared.b64 [%0], %1;" :: "r"(barL0), "r"(256u));
        asm volatile("mbarrier.init.shared.b64 [%0], %1;" :: "r"(barL1), "r"(256u));
    }
    __syncthreads();
    asm volatile("barrier.cluster.arrive.aligned;" ::: "memory");
    asm volatile("barrier.cluster.wait.aligned;" ::: "memory");

    unsigned remBar[2];
    remBar[0] = mapa_u32(barL0, peer);
    remBar[1] = mapa_u32(barL1, peer);

    int lane = tid & 31, wid = tid >> 5;
    int n0w = wid * 32;

    // hoist B fragments (gate-interleaved Ws): 8 kt x 4 n-tiles x 2 regs
    unsigned bfr[8][4][2];
    #pragma unroll
    for (int kt = 0; kt < 8; kt++) {
        int k0 = kt * 16;
        #pragma unroll
        for (int np = 0; np < 2; np++) {
            int rr = n0w + np * 16 + ((lane >> 4) << 3) + (lane & 7);
            int cc = k0 + (((lane >> 3) & 1) << 3);
            unsigned t4[4];
            ldsm4(t4, Ws + rr * 136 + cc);
            bfr[kt][np * 2][0] = t4[0]; bfr[kt][np * 2][1] = t4[1];
            bfr[kt][np * 2 + 1][0] = t4[2]; bfr[kt][np * 2 + 1][1] = t4[3];
        }
    }

    // this thread owns: row = lane>>2 (0..7), hidden cols jlA=8*wid+2*(lane&3), jlA+1
    int row = lane >> 2;
    int jlA = 8 * wid + 2 * (lane & 3);
    // remote half2 store addresses for each hbuf ping-pong buffer
    unsigned remHb[2];
    {
        unsigned base = smem_u32(hbuf);
        #pragma unroll
        for (int buf = 0; buf < 2; buf++) {
            unsigned loc = base + (unsigned)(((buf * 16 + row) * 136 + jbase + jlA) * 2);
            remHb[buf] = mapa_u32(loc, peer);
        }
    }

    float cstA = 0.f, cstB = 0.f;
    __half* hog = g_hh + (size_t)net * NROW * HH;
    int ph0 = 0, ph1 = 0;

    for (int t = 0; t < TT; t++) {
        bool haveNext = (t < TT - 1);
        uint4 pf;
        if (haveNext) {
            int prow = tid >> 5, rem = tid & 31, seg = rem >> 3, q = rem & 7;
            pf = *(const uint4*)(gxg + (size_t)((t + 1) * 256 + rb + prow) * 512
                                 + seg * 128 + jbase + q * 8);
        }
        // wait for peer's h-half from step t-1
        if (t > 0) {
            if ((t - 1) & 1) { mbar_wait_acq_cluster(barL1, (unsigned)ph1); ph1 ^= 1; }
            else             { mbar_wait_acq_cluster(barL0, (unsigned)ph0); ph0 ^= 1; }
        }

        // A fragments from full h (128 cols)
        const __half* hb = hbuf + (t & 1) * (16 * 136);
        unsigned A[8][4];
        #pragma unroll
        for (int kt = 0; kt < 8; kt++)
            ldsm4(A[kt], hb + (lane & 15) * 136 + kt * 16 + ((lane >> 4) << 3));

        float acc[4][4];
        #pragma unroll
        for (int nt = 0; nt < 4; nt++)
            #pragma unroll
            for (int q = 0; q < 4; q++) acc[nt][q] = 0.f;

        #pragma unroll
        for (int kt = 0; kt < 8; kt++)
            #pragma unroll
            for (int nt = 0; nt < 4; nt++)
                mma16816(acc[nt], A[kt], bfr[kt][nt]);

        // ---- register epilogue: nt == gate index for this thread's 2 cols ----
        {
            const __half* gxcur = gxs + (t & 1) * 2112;
            const __half* gp = gxcur + row * 264 + jlA;
            float2 f0 = __half22float2(*(const __half2*)(gp));
            float2 f1 = __half22float2(*(const __half2*)(gp + 64));
            float2 f2v = __half22float2(*(const __half2*)(gp + 128));
            float2 f3 = __half22float2(*(const __half2*)(gp + 192));

            float iA = sig_t(acc[0][0] + f0.x), iB = sig_t(acc[0][1] + f0.y);
            float fA = sig_t(acc[1][0] + f1.x), fB = sig_t(acc[1][1] + f1.y);
            float gA = tanh_t(acc[2][0] + f2v.x), gB = tanh_t(acc[2][1] + f2v.y);
            float oA = sig_t(acc[3][0] + f3.x), oB = sig_t(acc[3][1] + f3.y);

            float c2A = fA * cstA + iA * gA;
            float c2B = fB * cstB + iB * gB;
            float h2A = oA * tanh_t(c2A);
            float h2B = oB * tanh_t(c2B);

            *(__half2*)(hog + (size_t)(t * 256 + rb + row) * HH + jbase + jlA)
                = __floats2half2_rn(h2A, h2B);

            float m = ((maskb[t] >> row) & 1u) ? 0.f : 1.f;
            cstA = c2A * m;
            cstB = c2B * m;

            if (haveNext) {
                int nb = (t + 1) & 1;
                __half2 hm = __floats2half2_rn(h2A * m, h2B * m);
                *(__half2*)&hbuf[(nb * 16 + row) * 136 + jbase + jlA] = hm;
                st_cluster_u32(remHb[nb], *(unsigned*)&hm);
                // store prefetched gx for next step
                {
                    int prow = tid >> 5, rem = tid & 31, seg = rem >> 3, q = rem & 7;
                    ((uint4*)(gxs + nb * 2112))[33 * prow + 8 * seg + q] = pf;
                }
                mbar_arrive_rel_cluster(remBar[t & 1]);
            }
        }
        __syncthreads();
    }

    asm volatile("barrier.cluster.arrive.aligned;" ::: "memory");
    asm volatile("barrier.cluster.wait.aligned;" ::: "memory");
}

// ---------------- heads: warp per row, shfl reductions (fp16 h) ----------------
__global__ void __launch_bounds__(256) heads_kernel(
    const float* __restrict__ mw, const float* __restrict__ mb,
    const float* __restrict__ lw, const float* __restrict__ lb,
    const float* __restrict__ vw, const float* __restrict__ vb,
    float* __restrict__ out)
{
    __shared__ float ws[17][128];
    __shared__ float bs[17];
    int tid = threadIdx.x;
    for (int i = tid; i < 8 * 128; i += 256) {
        ws[i >> 7][i & 127]       = mw[i];
        ws[8 + (i >> 7)][i & 127] = lw[i];
    }
    for (int i = tid; i < 128; i += 256) ws[16][i] = vw[i];
    if (tid < 8) { bs[tid] = mb[tid]; bs[8 + tid] = lb[tid]; }
    if (tid == 16) bs[16] = vb[0];
    __syncthreads();

    int warp = tid >> 5, lane = tid & 31;
    int row = blockIdx.x * 8 + warp;

    const __half2* ha = (const __half2*)(g_hh + (size_t)row * HH) + lane * 2;
    const __half2* hc = (const __half2*)(g_hh + (size_t)NROW * HH + (size_t)row * HH) + lane * 2;
    float2 a0 = __half22float2(ha[0]);
    float2 a1 = __half22float2(ha[1]);
    float2 c0 = __half22float2(hc[0]);
    float2 c1 = __half22float2(hc[1]);

    float p[17];
    #pragma unroll
    for (int o = 0; o < 16; o++) {
        float4 wv = *(const float4*)(&ws[o][lane * 4]);
        p[o] = a0.x * wv.x + a0.y * wv.y + a1.x * wv.z + a1.y * wv.w;
    }
    {
        float4 wv = *(const float4*)(&ws[16][lane * 4]);
        p[16] = c0.x * wv.x + c0.y * wv.y + c1.x * wv.z + c1.y * wv.w;
    }
    #pragma unroll
    for (int o = 0; o < 17; o++) {
        p[o] += __shfl_xor_sync(0xffffffff, p[o], 16);
        p[o] += __shfl_xor_sync(0xffffffff, p[o], 8);
        p[o] += __shfl_xor_sync(0xffffffff, p[o], 4);
        p[o] += __shfl_xor_sync(0xffffffff, p[o], 2);
        p[o] += __shfl_xor_sync(0xffffffff, p[o], 1);
    }
    if (lane < 8) {
        out[(size_t)row * 8 + lane] = p[lane] + bs[lane];
    } else if (lane < 16) {
        out[(size_t)NROW * 8 + (size_t)row * 8 + (lane - 8)] = __expf(p[lane] + bs[lane]);
    } else if (lane == 16) {
        out[(size_t)NROW * 16 + row] = p[16] + bs[16];
    }
}

// ---------------- launch ----------------
extern "C" void kernel_launch(void* const* d_in, const int* in_sizes, int n_in,
                              void* d_out, int out_size)
{
    const float* state  = (const float*)d_in[0];
    const int*   dones  = (const int*)d_in[1];
    const float* a_w1   = (const float*)d_in[2];
    const float* a_b1   = (const float*)d_in[3];
    const float* a_w2   = (const float*)d_in[4];
    const float* a_b2   = (const float*)d_in[5];
    const float* c_w1   = (const float*)d_in[6];
    const float* c_b1   = (const float*)d_in[7];
    const float* c_w2   = (const float*)d_in[8];
    const float* c_b2   = (const float*)d_in[9];
    const float* a_wih  = (const float*)d_in[10];
    const float* a_whh  = (const float*)d_in[11];
    const float* a_bih  = (const float*)d_in[12];
    const float* a_bhh  = (const float*)d_in[13];
    const float* c_wih  = (const float*)d_in[14];
    const float* c_whh  = (const float*)d_in[15];
    const float* c_bih  = (const float*)d_in[16];
    const float* c_bhh  = (const float*)d_in[17];
    const float* mean_w = (const float*)d_in[18];
    const float* mean_b = (const float*)d_in[19];
    const float* lstd_w = (const float*)d_in[20];
    const float* lstd_b = (const float*)d_in[21];
    const float* val_w  = (const float*)d_in[22];
    const float* val_b  = (const float*)d_in[23];

    cudaFuncSetAttribute(fg_kernel, cudaFuncAttributeMaxDynamicSharedMemorySize, FG_SMEM);
    cudaFuncSetAttribute(lstm_cluster_kernel, cudaFuncAttributeMaxDynamicSharedMemorySize, LSTM_SMEM);

    pack16_kernel<<<512, 256>>>(a_wih, c_wih);

    dim3 fgg(1024, 2);
    fg_kernel<<<fgg, 256, FG_SMEM>>>(state,
                                     a_w1, a_b1, a_w2, a_b2,
                                     c_w1, c_b1, c_w2, c_b2,
                                     a_bih, a_bhh, c_bih, c_bhh);

    lstm_cluster_kernel<<<128, 256, LSTM_SMEM>>>(dones, a_whh, c_whh);

    heads_kernel<<<NROW / 8, 256>>>(mean_w, mean_b, lstd_w, lstd_b,
                                    val_w, val_b, (float*)d_out);
}

// round 8
// speedup vs baseline: 4.2264x; 1.2289x over previous
#include <cuda_runtime.h>
#include <cuda_fp16.h>

// Problem dims
#define TT 512
#define BB 256
#define SS 64
#define HH 128
#define NROW (TT*BB)          // 131072

// ---------------- scratch (device globals; no allocation allowed) ----------------
__device__ __half g_gxh[(size_t)2 * NROW * 512];     // gx fp16 (268MB)
__device__ __half g_hh [(size_t)2 * NROW * HH];      // LSTM hidden outputs fp16 (67MB)
__device__ __half g_wih16[2 * 512 * 128];            // wih packed fp16

// ---------------- helpers ----------------
__device__ __forceinline__ float tanh_t(float x) {
    float y; asm("tanh.approx.f32 %0, %1;" : "=f"(y) : "f"(x)); return y;
}
__device__ __forceinline__ float sig_t(float x) {
    return fmaf(tanh_t(x * 0.5f), 0.5f, 0.5f);
}
__device__ __forceinline__ void mma16816(float* c, const unsigned* a, const unsigned* b) {
    asm volatile(
        "mma.sync.aligned.m16n8k16.row.col.f32.f16.f16.f32 "
        "{%0,%1,%2,%3}, {%4,%5,%6,%7}, {%8,%9}, {%0,%1,%2,%3};\n"
        : "+f"(c[0]), "+f"(c[1]), "+f"(c[2]), "+f"(c[3])
        : "r"(a[0]), "r"(a[1]), "r"(a[2]), "r"(a[3]), "r"(b[0]), "r"(b[1]));
}
__device__ __forceinline__ void ldsm4(unsigned* d, const __half* p) {
    unsigned addr = (unsigned)__cvta_generic_to_shared((void*)p);
    asm volatile("ldmatrix.sync.aligned.m8n8.x4.shared.b16 {%0,%1,%2,%3}, [%4];\n"
                 : "=r"(d[0]), "=r"(d[1]), "=r"(d[2]), "=r"(d[3]) : "r"(addr));
}
__device__ __forceinline__ unsigned smem_u32(const void* p) {
    return (unsigned)__cvta_generic_to_shared((void*)p);
}
__device__ __forceinline__ void cpa16(void* smem_dst, const void* gsrc) {
    unsigned s = smem_u32(smem_dst);
    asm volatile("cp.async.cg.shared.global [%0], [%1], 16;" :: "r"(s), "l"(gsrc));
}
#define CP_COMMIT asm volatile("cp.async.commit_group;" ::: "memory")
#define CP_WAIT0  asm volatile("cp.async.wait_group 0;" ::: "memory")

__device__ __forceinline__ unsigned mapa_u32(unsigned addr, unsigned rank) {
    unsigned r;
    asm("mapa.shared::cluster.u32 %0, %1, %2;" : "=r"(r) : "r"(addr), "r"(rank));
    return r;
}
__device__ __forceinline__ void mbar_wait_acq_cluster(unsigned bar, unsigned parity) {
    asm volatile(
        "{\n\t.reg .pred P;\n"
        "W_%=:\n\t"
        "mbarrier.try_wait.parity.acquire.cluster.shared::cta.b64 P, [%0], %1;\n\t"
        "@P bra.uni D_%=;\n\t"
        "bra.uni W_%=;\n\t"
        "D_%=:\n\t}"
        :: "r"(bar), "r"(parity) : "memory");
}
__device__ __forceinline__ void mbar_arrive_rel_cluster(unsigned rem_bar) {
    asm volatile("mbarrier.arrive.release.cluster.shared::cluster.b64 _, [%0];"
                 :: "r"(rem_bar) : "memory");
}
__device__ __forceinline__ void st_cluster_u32(unsigned addr, unsigned v) {
    asm volatile("st.shared::cluster.b32 [%0], %1;" :: "r"(addr), "r"(v) : "memory");
}

// ---------------- pack wih -> fp16 ----------------
__global__ void pack16_kernel(const float* __restrict__ a_wih, const float* __restrict__ c_wih) {
    int idx = blockIdx.x * blockDim.x + threadIdx.x;
    if (idx >= 2 * 65536) return;
    int net = idx >> 16, r = idx & 65535;
    g_wih16[idx] = __float2half((net ? c_wih : a_wih)[r]);
}

// =====================================================================
// Fused feature kernel: f2 = relu(relu(X@W1.T+b1)@W2.T+b2) then
// gx = f2 @ wih.T + (bih+bhh). __launch_bounds__(256,2) -> <=128 regs,
// 2 CTA/SM. A frags re-ldsm'd from F2s per chunk (no 64-reg hoist).
// =====================================================================
#define XS_STR 72
#define MH_STR 136
#define FG_BS  0
#define FG_XS  3072
#define FG_W1S 21504
#define FG_W2S 39936
#define FG_C1S 74752
#define FG_SMEM 109568

__global__ void __launch_bounds__(256, 2) fg_kernel(
    const float* __restrict__ x,
    const float* __restrict__ a_w1, const float* __restrict__ a_b1,
    const float* __restrict__ a_w2, const float* __restrict__ a_b2,
    const float* __restrict__ c_w1, const float* __restrict__ c_b1,
    const float* __restrict__ c_w2, const float* __restrict__ c_b2,
    const float* __restrict__ a_bih, const float* __restrict__ a_bhh,
    const float* __restrict__ c_bih, const float* __restrict__ c_bhh)
{
    extern __shared__ __align__(16) char smraw[];
    float*  bs1  = (float*)(smraw + FG_BS);        // 128
    float*  bs2  = bs1 + 128;                      // 128
    float*  bsum = bs2 + 128;                      // 512
    __half* Xs   = (__half*)(smraw + FG_XS);       // stride 72
    __half* W1s  = (__half*)(smraw + FG_W1S);      // stride 72
    __half* W2s  = (__half*)(smraw + FG_W2S);      // stride 136
    __half* C1s  = (__half*)(smraw + FG_C1S);      // stride 136
    __half* F2s  = (__half*)(smraw + FG_XS);       // stride 136 (overlays Xs+W1s)
    __half* Wb[2]; Wb[0] = W2s; Wb[1] = C1s;

    int tid = threadIdx.x;
    int net = blockIdx.y;
    size_t rowbase = (size_t)blockIdx.x * 128;

    const float* w1 = net ? c_w1 : a_w1;
    const float* b1 = net ? c_b1 : a_b1;
    const float* w2 = net ? c_w2 : a_w2;
    const float* b2 = net ? c_b2 : a_b2;
    const float* bih = net ? c_bih : a_bih;
    const float* bhh = net ? c_bhh : a_bhh;

    {   // X [128][64]
        const float4* xg = (const float4*)(x + rowbase * SS);
        for (int i = tid; i < 128 * 16; i += 256) {
            int r = i >> 4, c4 = i & 15;
            float4 v = xg[(size_t)r * 16 + c4];
            *(__half2*)&Xs[r * XS_STR + c4 * 4]     = __floats2half2_rn(v.x, v.y);
            *(__half2*)&Xs[r * XS_STR + c4 * 4 + 2] = __floats2half2_rn(v.z, v.w);
        }
    }
    {   // W1 [128][64]
        const float4* wg = (const float4*)w1;
        for (int i = tid; i < 128 * 16; i += 256) {
            int r = i >> 4, c4 = i & 15;
            float4 v = wg[(size_t)r * 16 + c4];
            *(__half2*)&W1s[r * XS_STR + c4 * 4]     = __floats2half2_rn(v.x, v.y);
            *(__half2*)&W1s[r * XS_STR + c4 * 4 + 2] = __floats2half2_rn(v.z, v.w);
        }
    }
    {   // W2 [128][128]
        const float4* wg = (const float4*)w2;
        for (int i = tid; i < 128 * 32; i += 256) {
            int r = i >> 5, c4 = i & 31;
            float4 v = wg[(size_t)r * 32 + c4];
            *(__half2*)&W2s[r * MH_STR + c4 * 4]     = __floats2half2_rn(v.x, v.y);
            *(__half2*)&W2s[r * MH_STR + c4 * 4 + 2] = __floats2half2_rn(v.z, v.w);
        }
    }
    if (tid < 128) { bs1[tid] = __ldg(b1 + tid); bs2[tid] = __ldg(b2 + tid); }
    for (int i = tid; i < 512; i += 256) bsum[i] = __ldg(bih + i) + __ldg(bhh + i);
    __syncthreads();

    int wid = tid >> 5, lane = tid & 31;
    int warp_m = wid & 3, warp_n = wid >> 2;
    int m_base = warp_m * 32, n_base = warp_n * 64;

    float acc[2][8][4];

    // -------- stage A: C1 = relu(X @ W1.T + b1), K=64 --------
    #pragma unroll
    for (int mt = 0; mt < 2; mt++)
        #pragma unroll
        for (int nt = 0; nt < 8; nt++)
            #pragma unroll
            for (int q = 0; q < 4; q++) acc[mt][nt][q] = 0.f;

    #pragma unroll
    for (int kt = 0; kt < 4; kt++) {
        int k0 = kt * 16;
        unsigned a[2][4], b[8][2];
        #pragma unroll
        for (int mt = 0; mt < 2; mt++) {
            int r = m_base + mt * 16 + (lane & 15);
            int c = k0 + ((lane >> 4) << 3);
            ldsm4(a[mt], Xs + r * XS_STR + c);
        }
        #pragma unroll
        for (int np = 0; np < 4; np++) {
            int n0 = n_base + np * 16;
            int rr = n0 + ((lane >> 4) << 3) + (lane & 7);
            int cc = k0 + (((lane >> 3) & 1) << 3);
            unsigned t4[4];
            ldsm4(t4, W1s + rr * XS_STR + cc);
            b[np * 2][0] = t4[0]; b[np * 2][1] = t4[1];
            b[np * 2 + 1][0] = t4[2]; b[np * 2 + 1][1] = t4[3];
        }
        #pragma unroll
        for (int mt = 0; mt < 2; mt++)
            #pragma unroll
            for (int nt = 0; nt < 8; nt++)
                mma16816(acc[mt][nt], a[mt], b[nt]);
    }
    #pragma unroll
    for (int mt = 0; mt < 2; mt++) {
        #pragma unroll
        for (int nt = 0; nt < 8; nt++) {
            int r = m_base + mt * 16 + (lane >> 2);
            int c = n_base + nt * 8 + 2 * (lane & 3);
            float v0 = fmaxf(acc[mt][nt][0] + bs1[c], 0.f);
            float v1 = fmaxf(acc[mt][nt][1] + bs1[c + 1], 0.f);
            float v2 = fmaxf(acc[mt][nt][2] + bs1[c], 0.f);
            float v3 = fmaxf(acc[mt][nt][3] + bs1[c + 1], 0.f);
            *(__half2*)&C1s[r * MH_STR + c]       = __floats2half2_rn(v0, v1);
            *(__half2*)&C1s[(r + 8) * MH_STR + c] = __floats2half2_rn(v2, v3);
        }
    }
    __syncthreads();

    // -------- stage B: F2 = relu(C1 @ W2.T + b2), K=128 --------
    #pragma unroll
    for (int mt = 0; mt < 2; mt++)
        #pragma unroll
        for (int nt = 0; nt < 8; nt++)
            #pragma unroll
            for (int q = 0; q < 4; q++) acc[mt][nt][q] = 0.f;

    #pragma unroll
    for (int kt = 0; kt < 8; kt++) {
        int k0 = kt * 16;
        unsigned a[2][4], b[8][2];
        #pragma unroll
        for (int mt = 0; mt < 2; mt++) {
            int r = m_base + mt * 16 + (lane & 15);
            int c = k0 + ((lane >> 4) << 3);
            ldsm4(a[mt], C1s + r * MH_STR + c);
        }
        #pragma unroll
        for (int np = 0; np < 4; np++) {
            int n0 = n_base + np * 16;
            int rr = n0 + ((lane >> 4) << 3) + (lane & 7);
            int cc = k0 + (((lane >> 3) & 1) << 3);
            unsigned t4[4];
            ldsm4(t4, W2s + rr * MH_STR + cc);
            b[np * 2][0] = t4[0]; b[np * 2][1] = t4[1];
            b[np * 2 + 1][0] = t4[2]; b[np * 2 + 1][1] = t4[3];
        }
        #pragma unroll
        for (int mt = 0; mt < 2; mt++)
            #pragma unroll
            for (int nt = 0; nt < 8; nt++)
                mma16816(acc[mt][nt], a[mt], b[nt]);
    }
    // epilogue B -> F2s (smem, overlays Xs/W1s — dead after stage A/B barriers)
    #pragma unroll
    for (int mt = 0; mt < 2; mt++) {
        #pragma unroll
        for (int nt = 0; nt < 8; nt++) {
            int r = m_base + mt * 16 + (lane >> 2);
            int c = n_base + nt * 8 + 2 * (lane & 3);
            float v0 = fmaxf(acc[mt][nt][0] + bs2[c], 0.f);
            float v1 = fmaxf(acc[mt][nt][1] + bs2[c + 1], 0.f);
            float v2 = fmaxf(acc[mt][nt][2] + bs2[c], 0.f);
            float v3 = fmaxf(acc[mt][nt][3] + bs2[c + 1], 0.f);
            *(__half2*)&F2s[r * MH_STR + c]       = __floats2half2_rn(v0, v1);
            *(__half2*)&F2s[(r + 8) * MH_STR + c] = __floats2half2_rn(v2, v3);
        }
    }
    __syncthreads();   // F2s complete; W2s/C1s reads complete -> reuse as Wb

    // -------- gx phase: loop 4 weight chunks; A re-ldsm'd from F2s --------
    const __half* wsrc = g_wih16 + (size_t)net * 65536;

    // chunk 0 weights
    for (int i = tid; i < 2048; i += 256) {
        int r = i >> 4, c = i & 15;
        cpa16(Wb[0] + r * MH_STR + c * 8, wsrc + r * 128 + c * 8);
    }
    CP_COMMIT;
    CP_WAIT0;
    __syncthreads();

    __half* outp = g_gxh + (size_t)net * NROW * 512;

    #pragma unroll
    for (int ch = 0; ch < 4; ch++) {
        if (ch < 3) {
            const __half* src = wsrc + (ch + 1) * 128 * 128;
            __half* dst = Wb[(ch + 1) & 1];
            for (int i = tid; i < 2048; i += 256) {
                int r = i >> 4, c = i & 15;
                cpa16(dst + r * MH_STR + c * 8, src + r * 128 + c * 8);
            }
            CP_COMMIT;
        }
        const __half* Ws = Wb[ch & 1];

        #pragma unroll
        for (int mt = 0; mt < 2; mt++)
            #pragma unroll
            for (int nt = 0; nt < 8; nt++)
                #pragma unroll
                for (int q = 0; q < 4; q++) acc[mt][nt][q] = 0.f;

        #pragma unroll
        for (int kt = 0; kt < 8; kt++) {
            int k0 = kt * 16;
            unsigned a[2][4], b[8][2];
            #pragma unroll
            for (int mt = 0; mt < 2; mt++) {
                int r = m_base + mt * 16 + (lane & 15);
                int c = k0 + ((lane >> 4) << 3);
                ldsm4(a[mt], F2s + r * MH_STR + c);
            }
            #pragma unroll
            for (int np = 0; np < 4; np++) {
                int n0 = n_base + np * 16;
                int rr = n0 + ((lane >> 4) << 3) + (lane & 7);
                int cc = k0 + (((lane >> 3) & 1) << 3);
                unsigned t4[4];
                ldsm4(t4, Ws + rr * MH_STR + cc);
                b[np * 2][0] = t4[0]; b[np * 2][1] = t4[1];
                b[np * 2 + 1][0] = t4[2]; b[np * 2 + 1][1] = t4[3];
            }
            #pragma unroll
            for (int mt = 0; mt < 2; mt++)
                #pragma unroll
                for (int nt = 0; nt < 8; nt++)
                    mma16816(acc[mt][nt], a[mt], b[nt]);
        }
        #pragma unroll
        for (int mt = 0; mt < 2; mt++) {
            #pragma unroll
            for (int nt = 0; nt < 8; nt++) {
                int r = m_base + mt * 16 + (lane >> 2);
                int c = n_base + nt * 8 + 2 * (lane & 3);
                int gc = ch * 128 + c;
                float v0 = acc[mt][nt][0] + bsum[gc];
                float v1 = acc[mt][nt][1] + bsum[gc + 1];
                float v2 = acc[mt][nt][2] + bsum[gc];
                float v3 = acc[mt][nt][3] + bsum[gc + 1];
                *(__half2*)(outp + (rowbase + r) * (size_t)512 + gc) = __floats2half2_rn(v0, v1);
                *(__half2*)(outp + (rowbase + r + 8) * (size_t)512 + gc) = __floats2half2_rn(v2, v3);
            }
        }
        if (ch < 3) {
            CP_WAIT0;
            __syncthreads();
        }
    }
}

// =====================================================================
// LSTM recurrence, cluster-pair j-split, gate-interleaved Ws.
// Epilogue reordered: DSMEM peer store + release-arrive issued first
// (215-cyc DSMEM latency is the serial inter-step link), local/global
// stores after.
// =====================================================================
#define LW_WS  0
#define LW_HB  69632
#define LW_GX  78336
#define LW_MB  86784
#define LW_BAR 88832
#define LSTM_SMEM 88864

__global__ void __launch_bounds__(256) __cluster_dims__(2, 1, 1)
lstm_cluster_kernel(const int* __restrict__ dones,
                    const float* __restrict__ a_whh, const float* __restrict__ c_whh)
{
    extern __shared__ __align__(16) char sm[];
    __half*   Ws    = (__half*)(sm + LW_WS);
    __half*   hbuf  = (__half*)(sm + LW_HB);
    __half*   gxs   = (__half*)(sm + LW_GX);
    unsigned* maskb = (unsigned*)(sm + LW_MB);

    int tid = threadIdx.x;
    int bx  = blockIdx.x;
    int net = bx >> 6;
    int rowgroup = (bx >> 1) & 31;
    int rb = rowgroup << 3;                       // first of 8 batch rows
    unsigned rank;
    asm("mov.u32 %0, %%cluster_ctarank;" : "=r"(rank));
    unsigned peer = rank ^ 1u;
    int jbase = (int)rank * 64;
    const float* whh = net ? c_whh : a_whh;

    // ---- load gate-interleaved whh rows: n -> g=(n>>3)&3, jl=8*(n>>5)+(n&7) ----
    for (int i = tid; i < 256 * 32; i += 256) {
        int n = i >> 5, c4 = i & 31;
        int g  = (n >> 3) & 3;
        int jl = ((n >> 5) << 3) + (n & 7);
        int orig = g * 128 + jbase + jl;
        float4 v = ((const float4*)whh)[orig * 32 + c4];
        *(__half2*)&Ws[n * 136 + c4 * 4]     = __floats2half2_rn(v.x, v.y);
        *(__half2*)&Ws[n * 136 + c4 * 4 + 2] = __floats2half2_rn(v.z, v.w);
    }
    for (int i = tid; i < 2 * 16 * 136; i += 256) hbuf[i] = __float2half(0.f);
    for (int s = tid; s < 512; s += 256) {
        unsigned b = 0;
        #pragma unroll
        for (int r = 0; r < 8; r++) b |= ((unsigned)dones[s * 256 + rb + r] & 1u) << r;
        maskb[s] = b;
    }
    const __half* gxg = g_gxh + (size_t)net * NROW * 512;
    {
        int row = tid >> 5, rem = tid & 31, seg = rem >> 3, q = rem & 7;
        uint4 v = *(const uint4*)(gxg + (size_t)(rb + row) * 512 + seg * 128 + jbase + q * 8);
        ((uint4*)gxs)[33 * row + 8 * seg + q] = v;
    }
    unsigned barL0 = smem_u32(sm + LW_BAR);
    unsigned barL1 = barL0 + 8;
    if (tid == 0) {
        asm volatile("mbarrier.init.shared.b64 [%0], %1;" :: "r"(barL0), "r"(256u));
        asm volatile("mbarrier.init.shared.b64 [%0], %1;" :: "r"(barL1), "r"(256u));
    }
    __syncthreads();
    asm volatile("barrier.cluster.arrive.aligned;" ::: "memory");
    asm volatile("barrier.cluster.wait.aligned;" ::: "memory");

    unsigned remBar[2];
    remBar[0] = mapa_u32(barL0, peer);
    remBar[1] = mapa_u32(barL1, peer);

    int lane = tid & 31, wid = tid >> 5;
    int n0w = wid * 32;

    // hoist B fragments: 8 kt x 4 n-tiles x 2 regs
    unsigned bfr[8][4][2];
    #pragma unroll
    for (int kt = 0; kt < 8; kt++) {
        int k0 = kt * 16;
        #pragma unroll
        for (int np = 0; np < 2; np++) {
            int rr = n0w + np * 16 + ((lane >> 4) << 3) + (lane & 7);
            int cc = k0 + (((lane >> 3) & 1) << 3);
            unsigned t4[4];
            ldsm4(t4, Ws + rr * 136 + cc);
            bfr[kt][np * 2][0] = t4[0]; bfr[kt][np * 2][1] = t4[1];
            bfr[kt][np * 2 + 1][0] = t4[2]; bfr[kt][np * 2 + 1][1] = t4[3];
        }
    }

    int row = lane >> 2;
    int jlA = 8 * wid + 2 * (lane & 3);
    unsigned remHb[2];
    {
        unsigned base = smem_u32(hbuf);
        #pragma unroll
        for (int buf = 0; buf < 2; buf++) {
            unsigned loc = base + (unsigned)(((buf * 16 + row) * 136 + jbase + jlA) * 2);
            remHb[buf] = mapa_u32(loc, peer);
        }
    }

    float cstA = 0.f, cstB = 0.f;
    __half* hog = g_hh + (size_t)net * NROW * HH;
    int ph0 = 0, ph1 = 0;

    for (int t = 0; t < TT; t++) {
        bool haveNext = (t < TT - 1);
        uint4 pf;
        if (haveNext) {
            int prow = tid >> 5, rem = tid & 31, seg = rem >> 3, q = rem & 7;
            pf = *(const uint4*)(gxg + (size_t)((t + 1) * 256 + rb + prow) * 512
                                 + seg * 128 + jbase + q * 8);
        }
        if (t > 0) {
            if ((t - 1) & 1) { mbar_wait_acq_cluster(barL1, (unsigned)ph1); ph1 ^= 1; }
            else             { mbar_wait_acq_cluster(barL0, (unsigned)ph0); ph0 ^= 1; }
        }

        const __half* hb = hbuf + (t & 1) * (16 * 136);
        unsigned A[8][4];
        #pragma unroll
        for (int kt = 0; kt < 8; kt++)
            ldsm4(A[kt], hb + (lane & 15) * 136 + kt * 16 + ((lane >> 4) << 3));

        float acc[4][4];
        #pragma unroll
        for (int nt = 0; nt < 4; nt++)
            #pragma unroll
            for (int q = 0; q < 4; q++) acc[nt][q] = 0.f;

        #pragma unroll
        for (int kt = 0; kt < 8; kt++)
            #pragma unroll
            for (int nt = 0; nt < 4; nt++)
                mma16816(acc[nt], A[kt], bfr[kt][nt]);

        // ---- register epilogue; DSMEM push + arrive FIRST ----
        {
            const __half* gxcur = gxs + (t & 1) * 2112;
            const __half* gp = gxcur + row * 264 + jlA;
            float2 f0 = __half22float2(*(const __half2*)(gp));
            float2 f1 = __half22float2(*(const __half2*)(gp + 64));
            float2 f2v = __half22float2(*(const __half2*)(gp + 128));
            float2 f3 = __half22float2(*(const __half2*)(gp + 192));

            float iA = sig_t(acc[0][0] + f0.x), iB = sig_t(acc[0][1] + f0.y);
            float fA = sig_t(acc[1][0] + f1.x), fB = sig_t(acc[1][1] + f1.y);
            float gA = tanh_t(acc[2][0] + f2v.x), gB = tanh_t(acc[2][1] + f2v.y);
            float oA = sig_t(acc[3][0] + f3.x), oB = sig_t(acc[3][1] + f3.y);

            float c2A = fA * cstA + iA * gA;
            float c2B = fB * cstB + iB * gB;
            float h2A = oA * tanh_t(c2A);
            float h2B = oB * tanh_t(c2B);

            float m = ((maskb[t] >> row) & 1u) ? 0.f : 1.f;
            cstA = c2A * m;
            cstB = c2B * m;

            if (haveNext) {
                int nb = (t + 1) & 1;
                __half2 hm = __floats2half2_rn(h2A * m, h2B * m);
                // critical path first: remote push + release-arrive
                st_cluster_u32(remHb[nb], *(unsigned*)&hm);
                mbar_arrive_rel_cluster(remBar[t & 1]);
                // local (off critical path)
                *(__half2*)&hbuf[(nb * 16 + row) * 136 + jbase + jlA] = hm;
                {
                    int prow = tid >> 5, rem = tid & 31, seg = rem >> 3, q = rem & 7;
                    ((uint4*)(gxs + nb * 2112))[33 * prow + 8 * seg + q] = pf;
                }
            }
            *(__half2*)(hog + (size_t)(t * 256 + rb + row) * HH + jbase + jlA)
                = __floats2half2_rn(h2A, h2B);
        }
        __syncthreads();
    }

    asm volatile("barrier.cluster.arrive.aligned;" ::: "memory");
    asm volatile("barrier.cluster.wait.aligned;" ::: "memory");
}

// =====================================================================
// Heads on HMMA: 1 CTA per 128 rows; 8 warps x 16 rows.
// B matrix Wh[32][128]: rows 0-7 mean_w, 8-15 logstd_w, 16 val_w, rest 0.
// 24 mma/warp; register epilogue (bias, exp for std).
// =====================================================================
#define HD_HA 0
#define HD_HC 34816
#define HD_W  69632
#define HD_B  78336
#define HD_SMEM 78464

__global__ void __launch_bounds__(256) heads_mma_kernel(
    const float* __restrict__ mw, const float* __restrict__ mb,
    const float* __restrict__ lw, const float* __restrict__ lb,
    const float* __restrict__ vw, const float* __restrict__ vb,
    float* __restrict__ out)
{
    extern __shared__ __align__(16) char sm[];
    __half* Ha = (__half*)(sm + HD_HA);   // [128][136]
    __half* Hc = (__half*)(sm + HD_HC);   // [128][136]
    __half* Wh = (__half*)(sm + HD_W);    // [32][136]
    float*  bsm = (float*)(sm + HD_B);    // [0..7] mb, [8..15] lb, [16] vb

    int tid = threadIdx.x;
    size_t rowbase = (size_t)blockIdx.x * 128;

    const __half* ha = g_hh + rowbase * HH;
    const __half* hc = g_hh + (size_t)NROW * HH + rowbase * HH;
    for (int i = tid; i < 2048; i += 256) {
        int r = i >> 4, c = i & 15;
        cpa16(Ha + r * 136 + c * 8, ha + (size_t)r * HH + c * 8);
        cpa16(Hc + r * 136 + c * 8, hc + (size_t)r * HH + c * 8);
    }
    CP_COMMIT;
    for (int i = tid; i < 4096; i += 256) {
        int r = i >> 7, c = i & 127;
        float v = 0.f;
        if (r < 8) v = mw[r * 128 + c];
        else if (r < 16) v = lw[(r - 8) * 128 + c];
        else if (r == 16) v = vw[c];
        Wh[r * 136 + c] = __float2half(v);
    }
    if (tid < 8) { bsm[tid] = mb[tid]; bsm[8 + tid] = lb[tid]; }
    if (tid == 16) bsm[16] = vb[0];
    CP_WAIT0;
    __syncthreads();

    int wid = tid >> 5, lane = tid & 31;
    int r0 = wid * 16;

    // B fragments: nt0 = mean(cols 0-7), nt1 = logstd, nt2 = value(col 0)
    unsigned bf[8][3][2];
    #pragma unroll
    for (int kt = 0; kt < 8; kt++) {
        int k0 = kt * 16;
        {
            int rr = ((lane >> 4) << 3) + (lane & 7);
            int cc = k0 + (((lane >> 3) & 1) << 3);
            unsigned t4[4];
            ldsm4(t4, Wh + rr * 136 + cc);
            bf[kt][0][0] = t4[0]; bf[kt][0][1] = t4[1];
            bf[kt][1][0] = t4[2]; bf[kt][1][1] = t4[3];
        }
        {
            int rr = 16 + ((lane >> 4) << 3) + (lane & 7);
            int cc = k0 + (((lane >> 3) & 1) << 3);
            unsigned t4[4];
            ldsm4(t4, Wh + rr * 136 + cc);
            bf[kt][2][0] = t4[0]; bf[kt][2][1] = t4[1];
        }
    }

    float accM[4], accL[4], accV[4];
    #pragma unroll
    for (int q = 0; q < 4; q++) { accM[q] = 0.f; accL[q] = 0.f; accV[q] = 0.f; }

    #pragma unroll
    for (int kt = 0; kt < 8; kt++) {
        int k0 = kt * 16;
        unsigned a[4], cfr[4];
        ldsm4(a,   Ha + (r0 + (lane & 15)) * 136 + k0 + ((lane >> 4) << 3));
        ldsm4(cfr, Hc + (r0 + (lane & 15)) * 136 + k0 + ((lane >> 4) << 3));
        mma16816(accM, a, bf[kt][0]);
        mma16816(accL, a, bf[kt][1]);
        mma16816(accV, cfr, bf[kt][2]);
    }

    int row = lane >> 2, c0 = 2 * (lane & 3);
    size_t gr0 = rowbase + r0 + row;
    size_t gr1 = gr0 + 8;
    // mean
    *(float2*)(out + gr0 * 8 + c0) = make_float2(accM[0] + bsm[c0], accM[1] + bsm[c0 + 1]);
    *(float2*)(out + gr1 * 8 + c0) = make_float2(accM[2] + bsm[c0], accM[3] + bsm[c0 + 1]);
    // std = exp(logstd)
    float* outs = out + (size_t)NROW * 8;
    *(float2*)(outs + gr0 * 8 + c0) =
        make_float2(__expf(accL[0] + bsm[8 + c0]), __expf(accL[1] + bsm[8 + c0 + 1]));
    *(float2*)(outs + gr1 * 8 + c0) =
        make_float2(__expf(accL[2] + bsm[8 + c0]), __expf(accL[3] + bsm[8 + c0 + 1]));
    // value: column 0 of nt2 (threads with lane&3==0 hold cols 0,1)
    if ((lane & 3) == 0) {
        float* outv = out + (size_t)NROW * 16;
        outv[gr0] = accV[0] + bsm[16];
        outv[gr1] = accV[2] + bsm[16];
    }
}

// ---------------- launch ----------------
extern "C" void kernel_launch(void* const* d_in, const int* in_sizes, int n_in,
                              void* d_out, int out_size)
{
    const float* state  = (const float*)d_in[0];
    const int*   dones  = (const int*)d_in[1];
    const float* a_w1   = (const float*)d_in[2];
    const float* a_b1   = (const float*)d_in[3];
    const float* a_w2   = (const float*)d_in[4];
    const float* a_b2   = (const float*)d_in[5];
    const float* c_w1   = (const float*)d_in[6];
    const float* c_b1   = (const float*)d_in[7];
    const float* c_w2   = (const float*)d_in[8];
    const float* c_b2   = (const float*)d_in[9];
    const float* a_wih  = (const float*)d_in[10];
    const float* a_whh  = (const float*)d_in[11];
    const float* a_bih  = (const float*)d_in[12];
    const float* a_bhh  = (const float*)d_in[13];
    const float* c_wih  = (const float*)d_in[14];
    const float* c_whh  = (const float*)d_in[15];
    const float* c_bih  = (const float*)d_in[16];
    const float* c_bhh  = (const float*)d_in[17];
    const float* mean_w = (const float*)d_in[18];
    const float* mean_b = (const float*)d_in[19];
    const float* lstd_w = (const float*)d_in[20];
    const float* lstd_b = (const float*)d_in[21];
    const float* val_w  = (const float*)d_in[22];
    const float* val_b  = (const float*)d_in[23];

    cudaFuncSetAttribute(fg_kernel, cudaFuncAttributeMaxDynamicSharedMemorySize, FG_SMEM);
    cudaFuncSetAttribute(lstm_cluster_kernel, cudaFuncAttributeMaxDynamicSharedMemorySize, LSTM_SMEM);
    cudaFuncSetAttribute(heads_mma_kernel, cudaFuncAttributeMaxDynamicSharedMemorySize, HD_SMEM);

    pack16_kernel<<<512, 256>>>(a_wih, c_wih);

    dim3 fgg(1024, 2);
    fg_kernel<<<fgg, 256, FG_SMEM>>>(state,
                                     a_w1, a_b1, a_w2, a_b2,
                                     c_w1, c_b1, c_w2, c_b2,
                                     a_bih, a_bhh, c_bih, c_bhh);

    lstm_cluster_kernel<<<128, 256, LSTM_SMEM>>>(dones, a_whh, c_whh);

    heads_mma_kernel<<<1024, 256, HD_SMEM>>>(mean_w, mean_b, lstd_w, lstd_b,
                                             val_w, val_b, (float*)d_out);
}